// round 1
// baseline (speedup 1.0000x reference)
#include <cuda_runtime.h>
#include <math.h>

// ---------------- problem constants ----------------
#define BATCH   2
#define SEQLEN  1024
#define DMODEL  1024
#define DSTATE  128
#define DCONV   4
#define HEADDIM 64
#define DINNER  2048
#define NHEADS  32
#define CONVDIM 2304     // DINNER + 2*DSTATE
#define DINPROJ 4384     // 2*DINNER + 2*DSTATE + NHEADS
#define INTERD  2752
#define NTOK    2048     // BATCH*SEQLEN
#define EPSV    1e-6f

// ---------------- scratch (device globals: no cudaMalloc allowed) ----------------
__device__ float g_x1 [NTOK * DMODEL];
__device__ float g_Z  [NTOK * DINPROJ];
__device__ float g_xBC[NTOK * CONVDIM];
__device__ float g_y  [NTOK * DINNER];
__device__ float g_y2 [NTOK * DINNER];
__device__ float g_x2 [NTOK * DMODEL];
__device__ float g_h2 [NTOK * DMODEL];
__device__ float g_g  [NTOK * INTERD];
__device__ float g_u  [NTOK * INTERD];
__device__ float g_gu [NTOK * INTERD];

// ---------------- helpers ----------------
__device__ __forceinline__ float blockReduceSum(float v) {
    __shared__ float sb[32];
    int lane = threadIdx.x & 31;
    int w    = threadIdx.x >> 5;
    #pragma unroll
    for (int o = 16; o; o >>= 1) v += __shfl_xor_sync(0xffffffffu, v, o);
    if (lane == 0) sb[w] = v;
    __syncthreads();
    int nw = blockDim.x >> 5;
    float r = (threadIdx.x < (unsigned)nw) ? sb[threadIdx.x] : 0.f;
    if (w == 0) {
        #pragma unroll
        for (int o = 16; o; o >>= 1) r += __shfl_xor_sync(0xffffffffu, r, o);
        if (lane == 0) sb[0] = r;
    }
    __syncthreads();
    return sb[0];
}

__device__ __forceinline__ float siluf(float x) {
    return x * (1.0f / (1.0f + __expf(-x)));
}

// ---------------- rmsnorm over D=1024 (1 float4 / thread, 256 threads) ----------------
__global__ void __launch_bounds__(256) rmsnorm1024(const float* __restrict__ x,
                                                   const float* __restrict__ w,
                                                   float* __restrict__ out) {
    int tok = blockIdx.x;
    int tid = threadIdx.x;
    const float4* xp = (const float4*)(x + (size_t)tok * DMODEL);
    float4 v = xp[tid];
    float ss = v.x * v.x + v.y * v.y + v.z * v.z + v.w * v.w;
    ss = blockReduceSum(ss);
    float rs = rsqrtf(ss * (1.0f / DMODEL) + EPSV);
    float4 wv = ((const float4*)w)[tid];
    float4 o;
    o.x = v.x * rs * wv.x; o.y = v.y * rs * wv.y;
    o.z = v.z * rs * wv.z; o.w = v.w * rs * wv.w;
    ((float4*)(out + (size_t)tok * DMODEL))[tid] = o;
}

// ---------------- gated rmsnorm over D_INNER=2048: out = rmsnorm(y * silu(z)) * w ----------------
__global__ void __launch_bounds__(256) gated_rmsnorm(const float* __restrict__ y,
                                                     const float* __restrict__ Z,
                                                     const float* __restrict__ w,
                                                     float* __restrict__ out) {
    int tok = blockIdx.x;
    int tid = threadIdx.x;
    const float4* yp = (const float4*)(y + (size_t)tok * DINNER);
    const float4* zp = (const float4*)(Z + (size_t)tok * DINPROJ);  // z = first DINNER cols
    float4 v[2];
    float ss = 0.f;
    #pragma unroll
    for (int q = 0; q < 2; q++) {
        float4 yv = yp[tid + q * 256];
        float4 zv = zp[tid + q * 256];
        float4 t;
        t.x = yv.x * siluf(zv.x); t.y = yv.y * siluf(zv.y);
        t.z = yv.z * siluf(zv.z); t.w = yv.w * siluf(zv.w);
        v[q] = t;
        ss += t.x * t.x + t.y * t.y + t.z * t.z + t.w * t.w;
    }
    ss = blockReduceSum(ss);
    float rs = rsqrtf(ss * (1.0f / DINNER) + EPSV);
    #pragma unroll
    for (int q = 0; q < 2; q++) {
        float4 wv = ((const float4*)w)[tid + q * 256];
        float4 o;
        o.x = v[q].x * rs * wv.x; o.y = v[q].y * rs * wv.y;
        o.z = v[q].z * rs * wv.z; o.w = v[q].w * rs * wv.w;
        ((float4*)(out + (size_t)tok * DINNER))[tid + q * 256] = o;
    }
}

// ---------------- causal depthwise conv (width 4) + silu ----------------
// in: Z columns [DINNER, DINNER+CONVDIM) of each token row; out: xBC [NTOK][CONVDIM]
__global__ void __launch_bounds__(256) conv_silu(const float* __restrict__ Z,
                                                 const float* __restrict__ cw,
                                                 const float* __restrict__ cb,
                                                 float* __restrict__ out) {
    int c   = blockIdx.x * 256 + threadIdx.x;
    int tok = blockIdx.y;
    if (c >= CONVDIM) return;
    int l = tok & (SEQLEN - 1);
    float w0 = cw[c * 4 + 0], w1 = cw[c * 4 + 1], w2 = cw[c * 4 + 2], w3 = cw[c * 4 + 3];
    const float* zc = Z + (size_t)tok * DINPROJ + DINNER + c;  // tap at offset l
    float acc = cb[c];
    acc += zc[0] * w3;                                     // k=3 -> x[l]
    if (l >= 1) acc += zc[-(ptrdiff_t)DINPROJ]     * w2;   // x[l-1]
    if (l >= 2) acc += zc[-(ptrdiff_t)DINPROJ * 2] * w1;   // x[l-2]
    if (l >= 3) acc += zc[-(ptrdiff_t)DINPROJ * 3] * w0;   // x[l-3]
    out[(size_t)tok * CONVDIM + c] = siluf(acc);
}

// ---------------- sequential SSM scan ----------------
// grid: 128 blocks = (b, h, p-half); 128 threads, thread t owns state column n=t
// state hs[p] for 32 p-rows lives in registers.
__global__ void __launch_bounds__(128) ssm_scan(const float* __restrict__ xBC,
                                                const float* __restrict__ Z,
                                                const float* __restrict__ dt_bias,
                                                const float* __restrict__ A_log,
                                                const float* __restrict__ Dp,
                                                float* __restrict__ y) {
    int bid   = blockIdx.x;
    int b     = bid >> 6;
    int h     = (bid >> 1) & 31;
    int half  = bid & 1;
    int pbase = half * 32;
    int t     = threadIdx.x;

    __shared__ float s_dtx[32];
    __shared__ float s_x[32];
    __shared__ float s_partial[4][33];
    __shared__ float s_red[128][36];   // [t][p], stride 36 -> conflict-free column reads

    float hs[32];
    #pragma unroll
    for (int p = 0; p < 32; p++) hs[p] = 0.f;

    float Ah  = -__expf(A_log[h]);
    float dbh = dt_bias[h];
    float Dh  = Dp[h];
    int   p   = t & 31;
    int   j   = t >> 5;

    const float* xrow  = xBC + (size_t)b * SEQLEN * CONVDIM;
    const float* dtrow = Z + (size_t)b * SEQLEN * DINPROJ + (DINPROJ - NHEADS) + h;
    float*       yrow  = y + (size_t)b * SEQLEN * DINNER + h * HEADDIM + pbase;

    // prefetch step 0
    float Bv  = xrow[DINNER + t];
    float Cv  = xrow[DINNER + DSTATE + t];
    float dtr = dtrow[0];
    float xv  = (t < 32) ? xrow[h * HEADDIM + pbase + t] : 0.f;

    for (int l = 0; l < SEQLEN; l++) {
        float dts = dtr + dbh;
        float dt  = (dts > 20.f) ? dts : log1pf(__expf(dts));
        float dA  = __expf(dt * Ah);
        if (t < 32) { s_dtx[t] = dt * xv; s_x[t] = xv; }
        __syncthreads();

        // prefetch step l+1 (overlaps with compute below)
        float Bn = 0.f, Cn = 0.f, dtn = 0.f, xn = 0.f;
        if (l + 1 < SEQLEN) {
            const float* xr2 = xrow + (size_t)(l + 1) * CONVDIM;
            Bn  = xr2[DINNER + t];
            Cn  = xr2[DINNER + DSTATE + t];
            dtn = dtrow[(size_t)(l + 1) * DINPROJ];
            if (t < 32) xn = xr2[h * HEADDIM + pbase + t];
        }

        // state update + per-(p,n) contribution v = h*C
        #pragma unroll
        for (int pp = 0; pp < 32; pp += 4) {
            float4 d4 = *(const float4*)&s_dtx[pp];
            hs[pp + 0] = fmaf(hs[pp + 0], dA, d4.x * Bv);
            hs[pp + 1] = fmaf(hs[pp + 1], dA, d4.y * Bv);
            hs[pp + 2] = fmaf(hs[pp + 2], dA, d4.z * Bv);
            hs[pp + 3] = fmaf(hs[pp + 3], dA, d4.w * Bv);
            float4 v4;
            v4.x = hs[pp + 0] * Cv; v4.y = hs[pp + 1] * Cv;
            v4.z = hs[pp + 2] * Cv; v4.w = hs[pp + 3] * Cv;
            *(float4*)&s_red[t][pp] = v4;
        }
        __syncthreads();

        // reduce over n: thread (p, j) sums 32 rows of column p
        float sum = 0.f;
        #pragma unroll
        for (int i = 0; i < 32; i++) sum += s_red[j * 32 + i][p];
        s_partial[j][p] = sum;
        __syncthreads();

        if (t < 32) {
            float yv = s_partial[0][t] + s_partial[1][t] + s_partial[2][t] + s_partial[3][t];
            yrow[(size_t)l * DINNER + t] = yv + Dh * s_x[t];
        }

        Bv = Bn; Cv = Cn; dtr = dtn; xv = xn;
    }
}

// ---------------- fp32 GEMM: C[M,N] = A[M,K] @ W[N,K]^T (+ residual R[M,N]) ----------------
#define GBM 128
#define GBN 128
#define GBK 8
__global__ void __launch_bounds__(256) sgemm_tn(const float* __restrict__ A,
                                                const float* __restrict__ W,
                                                const float* __restrict__ R,
                                                float* __restrict__ C,
                                                int M, int N, int K) {
    __shared__ float As[GBK][GBM];
    __shared__ float Bs[GBK][GBN];
    int tid  = threadIdx.x;
    int row0 = blockIdx.y * GBM;
    int col0 = blockIdx.x * GBN;
    int lr   = tid >> 1;            // 0..127
    int lk   = (tid & 1) << 2;      // 0 or 4
    int tx   = tid & 15, ty = tid >> 4;

    float acc[8][8];
    #pragma unroll
    for (int i = 0; i < 8; i++)
        #pragma unroll
        for (int jj = 0; jj < 8; jj++) acc[i][jj] = 0.f;

    const float* Aptr = A + (size_t)(row0 + lr) * K + lk;
    int wn = col0 + lr;
    bool wok = wn < N;
    const float* Wptr = W + (size_t)(wok ? wn : 0) * K + lk;

    float4 av = *(const float4*)(Aptr);
    float4 bv = wok ? *(const float4*)(Wptr) : make_float4(0.f, 0.f, 0.f, 0.f);

    for (int k0 = 0; k0 < K; k0 += GBK) {
        As[lk + 0][lr] = av.x; As[lk + 1][lr] = av.y;
        As[lk + 2][lr] = av.z; As[lk + 3][lr] = av.w;
        Bs[lk + 0][lr] = bv.x; Bs[lk + 1][lr] = bv.y;
        Bs[lk + 2][lr] = bv.z; Bs[lk + 3][lr] = bv.w;
        __syncthreads();

        if (k0 + GBK < K) {
            av = *(const float4*)(Aptr + k0 + GBK);
            bv = wok ? *(const float4*)(Wptr + k0 + GBK) : make_float4(0.f, 0.f, 0.f, 0.f);
        }

        #pragma unroll
        for (int kk = 0; kk < GBK; kk++) {
            float a[8], bb[8];
            *(float4*)&a[0]  = *(const float4*)&As[kk][ty * 8];
            *(float4*)&a[4]  = *(const float4*)&As[kk][ty * 8 + 4];
            *(float4*)&bb[0] = *(const float4*)&Bs[kk][tx * 8];
            *(float4*)&bb[4] = *(const float4*)&Bs[kk][tx * 8 + 4];
            #pragma unroll
            for (int i = 0; i < 8; i++)
                #pragma unroll
                for (int jj = 0; jj < 8; jj++)
                    acc[i][jj] = fmaf(a[i], bb[jj], acc[i][jj]);
        }
        __syncthreads();
    }

    #pragma unroll
    for (int i = 0; i < 8; i++) {
        int r = row0 + ty * 8 + i;
        #pragma unroll
        for (int jj = 0; jj < 8; jj++) {
            int c = col0 + tx * 8 + jj;
            if (c < N) {
                float v = acc[i][jj];
                if (R) v += R[(size_t)r * N + c];
                C[(size_t)r * N + c] = v;
            }
        }
    }
}

// ---------------- elementwise swiglu: gu = silu(g) * u ----------------
__global__ void __launch_bounds__(256) swiglu_k(const float* __restrict__ g,
                                                const float* __restrict__ u,
                                                float* __restrict__ gu, int n) {
    int i = blockIdx.x * 256 + threadIdx.x;
    if (i < n) gu[i] = siluf(g[i]) * u[i];
}

// ---------------- launch ----------------
extern "C" void kernel_launch(void* const* d_in, const int* in_sizes, int n_in,
                              void* d_out, int out_size) {
    const float* hidden     = (const float*)d_in[0];
    const float* norm_w     = (const float*)d_in[1];
    const float* in_proj_w  = (const float*)d_in[2];
    const float* conv_w     = (const float*)d_in[3];
    const float* conv_b     = (const float*)d_in[4];
    const float* dt_bias    = (const float*)d_in[5];
    const float* A_log      = (const float*)d_in[6];
    const float* Dvec       = (const float*)d_in[7];
    const float* ssm_norm_w = (const float*)d_in[8];
    const float* out_proj_w = (const float*)d_in[9];
    const float* post_norm_w= (const float*)d_in[10];
    const float* gate_w     = (const float*)d_in[11];
    const float* up_w       = (const float*)d_in[12];
    const float* down_w     = (const float*)d_in[13];
    float* out = (float*)d_out;

    float *x1, *Z, *xBC, *y, *y2, *x2, *h2, *gg, *uu, *gu;
    cudaGetSymbolAddress((void**)&x1,  g_x1);
    cudaGetSymbolAddress((void**)&Z,   g_Z);
    cudaGetSymbolAddress((void**)&xBC, g_xBC);
    cudaGetSymbolAddress((void**)&y,   g_y);
    cudaGetSymbolAddress((void**)&y2,  g_y2);
    cudaGetSymbolAddress((void**)&x2,  g_x2);
    cudaGetSymbolAddress((void**)&h2,  g_h2);
    cudaGetSymbolAddress((void**)&gg,  g_g);
    cudaGetSymbolAddress((void**)&uu,  g_u);
    cudaGetSymbolAddress((void**)&gu,  g_gu);

    // 1. pre-norm
    rmsnorm1024<<<NTOK, 256>>>(hidden, norm_w, x1);
    // 2. in_proj: Z = x1 @ in_proj_w^T   [2048 x 4384]
    sgemm_tn<<<dim3((DINPROJ + GBN - 1) / GBN, NTOK / GBM), 256>>>(
        x1, in_proj_w, nullptr, Z, NTOK, DINPROJ, DMODEL);
    // 3. causal conv + silu over xBC channels
    conv_silu<<<dim3((CONVDIM + 255) / 256, NTOK), 256>>>(Z, conv_w, conv_b, xBC);
    // 4. sequential SSM scan (+ D skip)
    ssm_scan<<<128, 128>>>(xBC, Z, dt_bias, A_log, Dvec, y);
    // 5. gated rmsnorm: y2 = rmsnorm(y * silu(z)) * ssm_norm_w
    gated_rmsnorm<<<NTOK, 256>>>(y, Z, ssm_norm_w, y2);
    // 6. out_proj + residual: x2 = hidden + y2 @ out_proj_w^T
    sgemm_tn<<<dim3(DMODEL / GBN, NTOK / GBM), 256>>>(
        y2, out_proj_w, hidden, x2, NTOK, DMODEL, DINNER);
    // 7. post-norm
    rmsnorm1024<<<NTOK, 256>>>(x2, post_norm_w, h2);
    // 8. MLP gate / up
    sgemm_tn<<<dim3((INTERD + GBN - 1) / GBN, NTOK / GBM), 256>>>(
        h2, gate_w, nullptr, gg, NTOK, INTERD, DMODEL);
    sgemm_tn<<<dim3((INTERD + GBN - 1) / GBN, NTOK / GBM), 256>>>(
        h2, up_w, nullptr, uu, NTOK, INTERD, DMODEL);
    // 9. swiglu
    swiglu_k<<<(NTOK * INTERD) / 256, 256>>>(gg, uu, gu, NTOK * INTERD);
    // 10. down proj + residual: out = x2 + gu @ down_w^T
    sgemm_tn<<<dim3(DMODEL / GBN, NTOK / GBM), 256>>>(
        gu, down_w, x2, out, NTOK, DMODEL, INTERD);
}

// round 3
// speedup vs baseline: 1.8187x; 1.8187x over previous
#include <cuda_runtime.h>
#include <cuda_bf16.h>
#include <cstdint>
#include <math.h>

// ---------------- problem constants ----------------
#define BATCH   2
#define SEQLEN  1024
#define DMODEL  1024
#define DSTATE  128
#define DCONV   4
#define HEADDIM 64
#define DINNER  2048
#define NHEADS  32
#define CONVDIM 2304     // DINNER + 2*DSTATE
#define DINPROJ 4384     // 2*DINNER + 2*DSTATE + NHEADS
#define INTERD  2752
#define NTOK    2048     // BATCH*SEQLEN
#define EPSV    1e-6f

// ---------------- scratch (device globals: no cudaMalloc allowed) ----------------
__device__ float g_x1 [NTOK * DMODEL];
__device__ float g_Z  [NTOK * DINPROJ];
__device__ float g_xBC[NTOK * CONVDIM];
__device__ float g_y  [NTOK * DINNER];
__device__ float g_y2 [NTOK * DINNER];
__device__ float g_x2 [NTOK * DMODEL];
__device__ float g_h2 [NTOK * DMODEL];
__device__ float g_g  [NTOK * INTERD];
__device__ float g_u  [NTOK * INTERD];

// ---------------- helpers ----------------
__device__ __forceinline__ uint32_t smem_u32(const void* p) {
    uint32_t a;
    asm("{ .reg .u64 t; cvta.to.shared.u64 t, %1; cvt.u32.u64 %0, t; }" : "=r"(a) : "l"(p));
    return a;
}
__device__ __forceinline__ float blockReduceSum(float v) {
    __shared__ float sb[32];
    int lane = threadIdx.x & 31;
    int w    = threadIdx.x >> 5;
    #pragma unroll
    for (int o = 16; o; o >>= 1) v += __shfl_xor_sync(0xffffffffu, v, o);
    if (lane == 0) sb[w] = v;
    __syncthreads();
    int nw = blockDim.x >> 5;
    float r = (threadIdx.x < (unsigned)nw) ? sb[threadIdx.x] : 0.f;
    if (w == 0) {
        #pragma unroll
        for (int o = 16; o; o >>= 1) r += __shfl_xor_sync(0xffffffffu, r, o);
        if (lane == 0) sb[0] = r;
    }
    __syncthreads();
    return sb[0];
}
__device__ __forceinline__ float siluf(float x) { return x * (1.0f / (1.0f + __expf(-x))); }

__device__ __forceinline__ void ldsm4(uint32_t* r, uint32_t addr) {
    asm volatile("ldmatrix.sync.aligned.m8n8.x4.shared.b16 {%0,%1,%2,%3}, [%4];"
                 : "=r"(r[0]), "=r"(r[1]), "=r"(r[2]), "=r"(r[3]) : "r"(addr));
}
__device__ __forceinline__ void mma16816(float* d, const uint32_t* a, const uint32_t* b) {
    asm volatile(
        "mma.sync.aligned.m16n8k16.row.col.f32.bf16.bf16.f32 "
        "{%0,%1,%2,%3}, {%4,%5,%6,%7}, {%8,%9}, {%0,%1,%2,%3};"
        : "+f"(d[0]), "+f"(d[1]), "+f"(d[2]), "+f"(d[3])
        : "r"(a[0]), "r"(a[1]), "r"(a[2]), "r"(a[3]), "r"(b[0]), "r"(b[1]));
}
__device__ __forceinline__ void split_bf16(float a, float b, uint32_t& hi, uint32_t& lo) {
    __nv_bfloat16 ha = __float2bfloat16(a), hb = __float2bfloat16(b);
    __nv_bfloat16 la = __float2bfloat16(a - __bfloat162float(ha));
    __nv_bfloat16 lb = __float2bfloat16(b - __bfloat162float(hb));
    __nv_bfloat162 th(ha, hb), tl(la, lb);
    hi = *reinterpret_cast<uint32_t*>(&th);
    lo = *reinterpret_cast<uint32_t*>(&tl);
}

// ================= split-bf16 tensor-core GEMM (mma.sync, baseline PTX) =================
// C[M,N] = A[M,K] @ W[N,K]^T (+R); A optionally silu(A)*A2 (fused swiglu).
// 128x128 tile, Kc=32; 3 passes AhBh + AhBl + AlBh into fp32 accumulators.
#define KC 32
#define ROWB 40            // bf16 row stride (80B) -> conflict-free ldmatrix phases

__global__ void __launch_bounds__(256)
gemm_bf16s(const float* __restrict__ A, const float* __restrict__ A2,
           const float* __restrict__ W, const float* __restrict__ R,
           float* __restrict__ C, int M, int N, int K) {
    __shared__ __align__(16) __nv_bfloat16 sAh[128 * ROWB];
    __shared__ __align__(16) __nv_bfloat16 sAl[128 * ROWB];
    __shared__ __align__(16) __nv_bfloat16 sBh[128 * ROWB];
    __shared__ __align__(16) __nv_bfloat16 sBl[128 * ROWB];

    int tid  = threadIdx.x;
    int wid  = tid >> 5;
    int lane = tid & 31;
    int wr   = wid & 3;          // 4 warps along M (32 rows each)
    int wc   = wid >> 2;         // 2 warps along N (64 cols each)
    int row0 = blockIdx.y * 128;
    int col0 = blockIdx.x * 128;

    float acc[2][8][4];
    #pragma unroll
    for (int mt = 0; mt < 2; mt++)
        #pragma unroll
        for (int nt = 0; nt < 8; nt++)
            #pragma unroll
            for (int q = 0; q < 4; q++) acc[mt][nt][q] = 0.f;

    uint32_t bAh = smem_u32(sAh), bAl = smem_u32(sAl);
    uint32_t bBh = smem_u32(sBh), bBl = smem_u32(sBl);

    // ldmatrix lane address components
    int aRow  = wr * 32 + (lane & 15);            // + mt*16
    int aColB = ((lane >> 4) & 1) * 16;           // + ks*32
    int bRow  = wc * 64 + (lane & 7) + ((lane >> 4) & 1) * 8;  // + ntp*16
    int bColB = ((lane >> 3) & 1) * 16;           // + ks*32

    // per-thread global load slots: 4 float4 per tile per chunk
    int lrow[4], lc4[4];
    #pragma unroll
    for (int i = 0; i < 4; i++) {
        int f = i * 256 + tid;
        lrow[i] = f >> 3;          // 0..127
        lc4[i]  = (f & 7) * 4;     // float offset 0..28
    }

    float4 pa[4], pb[4];
    // prefetch chunk 0
    #pragma unroll
    for (int i = 0; i < 4; i++) {
        int r = lrow[i];
        float4 v = *(const float4*)(A + (size_t)(row0 + r) * K + lc4[i]);
        if (A2) {
            float4 u = *(const float4*)(A2 + (size_t)(row0 + r) * K + lc4[i]);
            v.x = siluf(v.x) * u.x; v.y = siluf(v.y) * u.y;
            v.z = siluf(v.z) * u.z; v.w = siluf(v.w) * u.w;
        }
        pa[i] = v;
        int wrow = col0 + r;
        pb[i] = (wrow < N) ? *(const float4*)(W + (size_t)wrow * K + lc4[i])
                           : make_float4(0.f, 0.f, 0.f, 0.f);
    }

    for (int k0 = 0; k0 < K; k0 += KC) {
        // store prefetched chunk to smem as hi/lo bf16
        #pragma unroll
        for (int i = 0; i < 4; i++) {
            int off = lrow[i] * ROWB + lc4[i];
            uint32_t h0, l0, h1, l1;
            split_bf16(pa[i].x, pa[i].y, h0, l0);
            split_bf16(pa[i].z, pa[i].w, h1, l1);
            *(uint2*)(sAh + off) = make_uint2(h0, h1);
            *(uint2*)(sAl + off) = make_uint2(l0, l1);
            split_bf16(pb[i].x, pb[i].y, h0, l0);
            split_bf16(pb[i].z, pb[i].w, h1, l1);
            *(uint2*)(sBh + off) = make_uint2(h0, h1);
            *(uint2*)(sBl + off) = make_uint2(l0, l1);
        }
        __syncthreads();

        // prefetch next chunk (overlaps with mma below)
        if (k0 + KC < K) {
            #pragma unroll
            for (int i = 0; i < 4; i++) {
                int r = lrow[i];
                float4 v = *(const float4*)(A + (size_t)(row0 + r) * K + k0 + KC + lc4[i]);
                if (A2) {
                    float4 u = *(const float4*)(A2 + (size_t)(row0 + r) * K + k0 + KC + lc4[i]);
                    v.x = siluf(v.x) * u.x; v.y = siluf(v.y) * u.y;
                    v.z = siluf(v.z) * u.z; v.w = siluf(v.w) * u.w;
                }
                pa[i] = v;
                int wrow = col0 + r;
                pb[i] = (wrow < N) ? *(const float4*)(W + (size_t)wrow * K + k0 + KC + lc4[i])
                                   : make_float4(0.f, 0.f, 0.f, 0.f);
            }
        }

        // mma over 2 k16-steps, 3 passes each
        #pragma unroll
        for (int ks = 0; ks < 2; ks++) {
            uint32_t Ah[2][4], Al[2][4], Bh[4][4], Bl[4][4];
            #pragma unroll
            for (int mt = 0; mt < 2; mt++) {
                uint32_t off = (uint32_t)((aRow + mt * 16) * (ROWB * 2) + ks * 32 + aColB);
                ldsm4(Ah[mt], bAh + off);
                ldsm4(Al[mt], bAl + off);
            }
            #pragma unroll
            for (int ntp = 0; ntp < 4; ntp++) {
                uint32_t off = (uint32_t)((bRow + ntp * 16) * (ROWB * 2) + ks * 32 + bColB);
                ldsm4(Bh[ntp], bBh + off);
                ldsm4(Bl[ntp], bBl + off);
            }
            #pragma unroll
            for (int mt = 0; mt < 2; mt++)
                #pragma unroll
                for (int ntp = 0; ntp < 4; ntp++) {
                    mma16816(acc[mt][ntp * 2 + 0], Ah[mt], &Bh[ntp][0]);
                    mma16816(acc[mt][ntp * 2 + 1], Ah[mt], &Bh[ntp][2]);
                }
            #pragma unroll
            for (int mt = 0; mt < 2; mt++)
                #pragma unroll
                for (int ntp = 0; ntp < 4; ntp++) {
                    mma16816(acc[mt][ntp * 2 + 0], Ah[mt], &Bl[ntp][0]);
                    mma16816(acc[mt][ntp * 2 + 1], Ah[mt], &Bl[ntp][2]);
                }
            #pragma unroll
            for (int mt = 0; mt < 2; mt++)
                #pragma unroll
                for (int ntp = 0; ntp < 4; ntp++) {
                    mma16816(acc[mt][ntp * 2 + 0], Al[mt], &Bh[ntp][0]);
                    mma16816(acc[mt][ntp * 2 + 1], Al[mt], &Bh[ntp][2]);
                }
        }
        __syncthreads();
    }

    // ---- epilogue ----
    int gid = lane >> 2;    // 0..7
    int tig = lane & 3;     // 0..3
    #pragma unroll
    for (int mt = 0; mt < 2; mt++) {
        int r0 = row0 + wr * 32 + mt * 16 + gid;
        #pragma unroll
        for (int nt = 0; nt < 8; nt++) {
            int col = col0 + wc * 64 + nt * 8 + tig * 2;
            if (col < N) {
                float2 v0 = make_float2(acc[mt][nt][0], acc[mt][nt][1]);
                float2 v1 = make_float2(acc[mt][nt][2], acc[mt][nt][3]);
                if (R) {
                    float2 r0v = *(const float2*)(R + (size_t)r0 * N + col);
                    float2 r1v = *(const float2*)(R + (size_t)(r0 + 8) * N + col);
                    v0.x += r0v.x; v0.y += r0v.y;
                    v1.x += r1v.x; v1.y += r1v.y;
                }
                *(float2*)(C + (size_t)r0 * N + col)       = v0;
                *(float2*)(C + (size_t)(r0 + 8) * N + col) = v1;
            }
        }
    }
}

// ---------------- rmsnorm over D=1024 ----------------
__global__ void __launch_bounds__(256) rmsnorm1024(const float* __restrict__ x,
                                                   const float* __restrict__ w,
                                                   float* __restrict__ out) {
    int tok = blockIdx.x;
    int tid = threadIdx.x;
    const float4* xp = (const float4*)(x + (size_t)tok * DMODEL);
    float4 v = xp[tid];
    float ss = v.x * v.x + v.y * v.y + v.z * v.z + v.w * v.w;
    ss = blockReduceSum(ss);
    float rs = rsqrtf(ss * (1.0f / DMODEL) + EPSV);
    float4 wv = ((const float4*)w)[tid];
    float4 o;
    o.x = v.x * rs * wv.x; o.y = v.y * rs * wv.y;
    o.z = v.z * rs * wv.z; o.w = v.w * rs * wv.w;
    ((float4*)(out + (size_t)tok * DMODEL))[tid] = o;
}

// ---------------- gated rmsnorm over D_INNER=2048 ----------------
__global__ void __launch_bounds__(256) gated_rmsnorm(const float* __restrict__ y,
                                                     const float* __restrict__ Z,
                                                     const float* __restrict__ w,
                                                     float* __restrict__ out) {
    int tok = blockIdx.x;
    int tid = threadIdx.x;
    const float4* yp = (const float4*)(y + (size_t)tok * DINNER);
    const float4* zp = (const float4*)(Z + (size_t)tok * DINPROJ);
    float4 v[2];
    float ss = 0.f;
    #pragma unroll
    for (int q = 0; q < 2; q++) {
        float4 yv = yp[tid + q * 256];
        float4 zv = zp[tid + q * 256];
        float4 t;
        t.x = yv.x * siluf(zv.x); t.y = yv.y * siluf(zv.y);
        t.z = yv.z * siluf(zv.z); t.w = yv.w * siluf(zv.w);
        v[q] = t;
        ss += t.x * t.x + t.y * t.y + t.z * t.z + t.w * t.w;
    }
    ss = blockReduceSum(ss);
    float rs = rsqrtf(ss * (1.0f / DINNER) + EPSV);
    #pragma unroll
    for (int q = 0; q < 2; q++) {
        float4 wv = ((const float4*)w)[tid + q * 256];
        float4 o;
        o.x = v[q].x * rs * wv.x; o.y = v[q].y * rs * wv.y;
        o.z = v[q].z * rs * wv.z; o.w = v[q].w * rs * wv.w;
        ((float4*)(out + (size_t)tok * DINNER))[tid + q * 256] = o;
    }
}

// ---------------- causal depthwise conv (width 4) + silu ----------------
__global__ void __launch_bounds__(256) conv_silu(const float* __restrict__ Z,
                                                 const float* __restrict__ cw,
                                                 const float* __restrict__ cb,
                                                 float* __restrict__ out) {
    int c   = blockIdx.x * 256 + threadIdx.x;
    int tok = blockIdx.y;
    if (c >= CONVDIM) return;
    int l = tok & (SEQLEN - 1);
    float w0 = cw[c * 4 + 0], w1 = cw[c * 4 + 1], w2 = cw[c * 4 + 2], w3 = cw[c * 4 + 3];
    const float* zc = Z + (size_t)tok * DINPROJ + DINNER + c;
    float acc = cb[c];
    acc += zc[0] * w3;
    if (l >= 1) acc += zc[-(ptrdiff_t)DINPROJ]     * w2;
    if (l >= 2) acc += zc[-(ptrdiff_t)DINPROJ * 2] * w1;
    if (l >= 3) acc += zc[-(ptrdiff_t)DINPROJ * 3] * w0;
    out[(size_t)tok * CONVDIM + c] = siluf(acc);
}

// ---------------- sequential SSM scan (2-step unrolled) ----------------
__global__ void __launch_bounds__(128) ssm_scan(const float* __restrict__ xBC,
                                                const float* __restrict__ Z,
                                                const float* __restrict__ dt_bias,
                                                const float* __restrict__ A_log,
                                                const float* __restrict__ Dp,
                                                float* __restrict__ y) {
    int bid   = blockIdx.x;
    int b     = bid >> 6;
    int h     = (bid >> 1) & 31;
    int half  = bid & 1;
    int pbase = half * 32;
    int t     = threadIdx.x;

    __shared__ float s_dtx[2][32];
    __shared__ float s_x[2][32];
    __shared__ float s_partial[2][4][33];
    __shared__ float s_red[2][128][36];

    float hs[32];
    #pragma unroll
    for (int p = 0; p < 32; p++) hs[p] = 0.f;

    float Ah  = -__expf(A_log[h]);
    float dbh = dt_bias[h];
    float Dh  = Dp[h];
    int   p   = t & 31;
    int   j   = t >> 5;

    const float* xrow  = xBC + (size_t)b * SEQLEN * CONVDIM;
    const float* dtrow = Z + (size_t)b * SEQLEN * DINPROJ + (DINPROJ - NHEADS) + h;
    float*       yrow  = y + (size_t)b * SEQLEN * DINNER + h * HEADDIM + pbase;

    float Bv[2], Cv[2], dtr[2], xv[2];
    #pragma unroll
    for (int q = 0; q < 2; q++) {
        const float* xr = xrow + (size_t)q * CONVDIM;
        Bv[q]  = xr[DINNER + t];
        Cv[q]  = xr[DINNER + DSTATE + t];
        dtr[q] = dtrow[(size_t)q * DINPROJ];
        xv[q]  = (t < 32) ? xr[h * HEADDIM + pbase + t] : 0.f;
    }

    for (int l = 0; l < SEQLEN; l += 2) {
        float dA[2], dtv[2];
        #pragma unroll
        for (int q = 0; q < 2; q++) {
            float dts = dtr[q] + dbh;
            dtv[q] = (dts > 20.f) ? dts : log1pf(__expf(dts));
            dA[q]  = __expf(dtv[q] * Ah);
        }
        if (t < 32) {
            s_dtx[0][t] = dtv[0] * xv[0]; s_x[0][t] = xv[0];
            s_dtx[1][t] = dtv[1] * xv[1]; s_x[1][t] = xv[1];
        }
        __syncthreads();

        float Bn[2], Cn[2], dtn[2], xn[2];
        #pragma unroll
        for (int q = 0; q < 2; q++) {
            int s = l + 2 + q;
            Bn[q] = Cn[q] = dtn[q] = xn[q] = 0.f;
            if (s < SEQLEN) {
                const float* xr = xrow + (size_t)s * CONVDIM;
                Bn[q]  = xr[DINNER + t];
                Cn[q]  = xr[DINNER + DSTATE + t];
                dtn[q] = dtrow[(size_t)s * DINPROJ];
                if (t < 32) xn[q] = xr[h * HEADDIM + pbase + t];
            }
        }

        #pragma unroll
        for (int q = 0; q < 2; q++) {
            float dAq = dA[q], Bq = Bv[q], Cq = Cv[q];
            #pragma unroll
            for (int pp = 0; pp < 32; pp += 4) {
                float4 d4 = *(const float4*)&s_dtx[q][pp];
                hs[pp + 0] = fmaf(hs[pp + 0], dAq, d4.x * Bq);
                hs[pp + 1] = fmaf(hs[pp + 1], dAq, d4.y * Bq);
                hs[pp + 2] = fmaf(hs[pp + 2], dAq, d4.z * Bq);
                hs[pp + 3] = fmaf(hs[pp + 3], dAq, d4.w * Bq);
                float4 v4;
                v4.x = hs[pp + 0] * Cq; v4.y = hs[pp + 1] * Cq;
                v4.z = hs[pp + 2] * Cq; v4.w = hs[pp + 3] * Cq;
                *(float4*)&s_red[q][t][pp] = v4;
            }
        }
        __syncthreads();

        #pragma unroll
        for (int q = 0; q < 2; q++) {
            float sum = 0.f;
            #pragma unroll
            for (int i = 0; i < 32; i++) sum += s_red[q][j * 32 + i][p];
            s_partial[q][j][p] = sum;
        }
        __syncthreads();

        if (t < 32) {
            #pragma unroll
            for (int q = 0; q < 2; q++) {
                float yv = s_partial[q][0][t] + s_partial[q][1][t]
                         + s_partial[q][2][t] + s_partial[q][3][t];
                yrow[(size_t)(l + q) * DINNER + t] = yv + Dh * s_x[q][t];
            }
        }

        #pragma unroll
        for (int q = 0; q < 2; q++) { Bv[q] = Bn[q]; Cv[q] = Cn[q]; dtr[q] = dtn[q]; xv[q] = xn[q]; }
    }
}

// ---------------- launch ----------------
extern "C" void kernel_launch(void* const* d_in, const int* in_sizes, int n_in,
                              void* d_out, int out_size) {
    const float* hidden     = (const float*)d_in[0];
    const float* norm_w     = (const float*)d_in[1];
    const float* in_proj_w  = (const float*)d_in[2];
    const float* conv_w     = (const float*)d_in[3];
    const float* conv_b     = (const float*)d_in[4];
    const float* dt_bias    = (const float*)d_in[5];
    const float* A_log      = (const float*)d_in[6];
    const float* Dvec       = (const float*)d_in[7];
    const float* ssm_norm_w = (const float*)d_in[8];
    const float* out_proj_w = (const float*)d_in[9];
    const float* post_norm_w= (const float*)d_in[10];
    const float* gate_w     = (const float*)d_in[11];
    const float* up_w       = (const float*)d_in[12];
    const float* down_w     = (const float*)d_in[13];
    float* out = (float*)d_out;

    float *x1, *Z, *xBC, *y, *y2, *x2, *h2, *gg, *uu;
    cudaGetSymbolAddress((void**)&x1,  g_x1);
    cudaGetSymbolAddress((void**)&Z,   g_Z);
    cudaGetSymbolAddress((void**)&xBC, g_xBC);
    cudaGetSymbolAddress((void**)&y,   g_y);
    cudaGetSymbolAddress((void**)&y2,  g_y2);
    cudaGetSymbolAddress((void**)&x2,  g_x2);
    cudaGetSymbolAddress((void**)&h2,  g_h2);
    cudaGetSymbolAddress((void**)&gg,  g_g);
    cudaGetSymbolAddress((void**)&uu,  g_u);

    // 1. pre-norm
    rmsnorm1024<<<NTOK, 256>>>(hidden, norm_w, x1);
    // 2. in_proj: Z = x1 @ in_proj_w^T   [2048 x 4384]
    gemm_bf16s<<<dim3((DINPROJ + 127) / 128, NTOK / 128), 256>>>(
        x1, nullptr, in_proj_w, nullptr, Z, NTOK, DINPROJ, DMODEL);
    // 3. causal conv + silu
    conv_silu<<<dim3((CONVDIM + 255) / 256, NTOK), 256>>>(Z, conv_w, conv_b, xBC);
    // 4. sequential SSM scan (+ D skip)
    ssm_scan<<<128, 128>>>(xBC, Z, dt_bias, A_log, Dvec, y);
    // 5. gated rmsnorm
    gated_rmsnorm<<<NTOK, 256>>>(y, Z, ssm_norm_w, y2);
    // 6. out_proj + residual
    gemm_bf16s<<<dim3(DMODEL / 128, NTOK / 128), 256>>>(
        y2, nullptr, out_proj_w, hidden, x2, NTOK, DMODEL, DINNER);
    // 7. post-norm
    rmsnorm1024<<<NTOK, 256>>>(x2, post_norm_w, h2);
    // 8. MLP gate / up
    gemm_bf16s<<<dim3((INTERD + 127) / 128, NTOK / 128), 256>>>(
        h2, nullptr, gate_w, nullptr, gg, NTOK, INTERD, DMODEL);
    gemm_bf16s<<<dim3((INTERD + 127) / 128, NTOK / 128), 256>>>(
        h2, nullptr, up_w, nullptr, uu, NTOK, INTERD, DMODEL);
    // 9+10. fused swiglu + down proj + residual
    gemm_bf16s<<<dim3(DMODEL / 128, NTOK / 128), 256>>>(
        gg, uu, down_w, x2, out, NTOK, DMODEL, INTERD);
}

// round 4
// speedup vs baseline: 1.8960x; 1.0425x over previous
#include <cuda_runtime.h>
#include <cuda_bf16.h>
#include <cstdint>
#include <math.h>

// ---------------- problem constants ----------------
#define BATCH   2
#define SEQLEN  1024
#define DMODEL  1024
#define DSTATE  128
#define DCONV   4
#define HEADDIM 64
#define DINNER  2048
#define NHEADS  32
#define CONVDIM 2304     // DINNER + 2*DSTATE
#define DINPROJ 4384     // 2*DINNER + 2*DSTATE + NHEADS
#define INTERD  2752
#define NTOK    2048     // BATCH*SEQLEN
#define EPSV    1e-6f

// ---------------- fp32 scratch ----------------
__device__ float g_Z  [NTOK * DINPROJ];
__device__ float g_xBC[NTOK * CONVDIM];
__device__ float g_y  [NTOK * DINNER];
__device__ float g_x2 [NTOK * DMODEL];
__device__ float g_g  [NTOK * INTERD];

// ---------------- split-bf16 activations ----------------
__device__ __nv_bfloat16 g_x1h[NTOK * DMODEL], g_x1l[NTOK * DMODEL];
__device__ __nv_bfloat16 g_h2h[NTOK * DMODEL], g_h2l[NTOK * DMODEL];
__device__ __nv_bfloat16 g_y2h[NTOK * DINNER], g_y2l[NTOK * DINNER];
__device__ __nv_bfloat16 g_ddh[NTOK * INTERD], g_ddl[NTOK * INTERD];

// ---------------- split-bf16 weights ----------------
__device__ __nv_bfloat16 g_wih[DINPROJ * DMODEL], g_wil[DINPROJ * DMODEL];
__device__ __nv_bfloat16 g_woh[DMODEL * DINNER],  g_wol[DMODEL * DINNER];
__device__ __nv_bfloat16 g_wgh[INTERD * DMODEL],  g_wgl[INTERD * DMODEL];
__device__ __nv_bfloat16 g_wuh[INTERD * DMODEL],  g_wul[INTERD * DMODEL];
__device__ __nv_bfloat16 g_wdh[DMODEL * INTERD],  g_wdl[DMODEL * INTERD];

// ---------------- helpers ----------------
__device__ __forceinline__ uint32_t smem_u32(const void* p) {
    uint32_t a;
    asm("{ .reg .u64 t; cvta.to.shared.u64 t, %1; cvt.u32.u64 %0, t; }" : "=r"(a) : "l"(p));
    return a;
}
__device__ __forceinline__ float blockReduceSum(float v) {
    __shared__ float sb[32];
    int lane = threadIdx.x & 31;
    int w    = threadIdx.x >> 5;
    #pragma unroll
    for (int o = 16; o; o >>= 1) v += __shfl_xor_sync(0xffffffffu, v, o);
    if (lane == 0) sb[w] = v;
    __syncthreads();
    int nw = blockDim.x >> 5;
    float r = (threadIdx.x < (unsigned)nw) ? sb[threadIdx.x] : 0.f;
    if (w == 0) {
        #pragma unroll
        for (int o = 16; o; o >>= 1) r += __shfl_xor_sync(0xffffffffu, r, o);
        if (lane == 0) sb[0] = r;
    }
    __syncthreads();
    return sb[0];
}
__device__ __forceinline__ float siluf(float x) { return x * (1.0f / (1.0f + __expf(-x))); }

__device__ __forceinline__ void ldsm4(uint32_t* r, uint32_t addr) {
    asm volatile("ldmatrix.sync.aligned.m8n8.x4.shared.b16 {%0,%1,%2,%3}, [%4];"
                 : "=r"(r[0]), "=r"(r[1]), "=r"(r[2]), "=r"(r[3]) : "r"(addr));
}
__device__ __forceinline__ void mma16816(float* d, const uint32_t* a, const uint32_t* b) {
    asm volatile(
        "mma.sync.aligned.m16n8k16.row.col.f32.bf16.bf16.f32 "
        "{%0,%1,%2,%3}, {%4,%5,%6,%7}, {%8,%9}, {%0,%1,%2,%3};"
        : "+f"(d[0]), "+f"(d[1]), "+f"(d[2]), "+f"(d[3])
        : "r"(a[0]), "r"(a[1]), "r"(a[2]), "r"(a[3]), "r"(b[0]), "r"(b[1]));
}
__device__ __forceinline__ void split_bf16(float a, float b, uint32_t& hi, uint32_t& lo) {
    __nv_bfloat16 ha = __float2bfloat16(a), hb = __float2bfloat16(b);
    __nv_bfloat16 la = __float2bfloat16(a - __bfloat162float(ha));
    __nv_bfloat16 lb = __float2bfloat16(b - __bfloat162float(hb));
    __nv_bfloat162 th(ha, hb), tl(la, lb);
    hi = *reinterpret_cast<uint32_t*>(&th);
    lo = *reinterpret_cast<uint32_t*>(&tl);
}

// ---------------- fp32 -> split-bf16 converter ----------------
__global__ void __launch_bounds__(256) f32_split(const float* __restrict__ in,
                                                 __nv_bfloat16* __restrict__ oh,
                                                 __nv_bfloat16* __restrict__ ol, int n4) {
    int i = blockIdx.x * 256 + threadIdx.x;
    if (i < n4) {
        float4 v = ((const float4*)in)[i];
        uint32_t h0, l0, h1, l1;
        split_bf16(v.x, v.y, h0, l0);
        split_bf16(v.z, v.w, h1, l1);
        ((uint2*)oh)[i] = make_uint2(h0, h1);
        ((uint2*)ol)[i] = make_uint2(l0, l1);
    }
}

// ================= split-bf16 tensor-core GEMM (preconverted inputs) =================
// C[M,N] = (Ah+Al)[M,K] @ (Wh+Wl)[N,K]^T via 3 passes (AhBh + AhBl + AlBh).
// Epilogue modes: +R residual; G companion: out = silu(G)*acc; output fp32 (Cf) or split-bf16 (Ch,Cl).
#define KC 32
#define ROWB 40

__global__ void __launch_bounds__(256)
gemm_bf16(const __nv_bfloat16* __restrict__ Ah_, const __nv_bfloat16* __restrict__ Al_,
          const __nv_bfloat16* __restrict__ Wh_, const __nv_bfloat16* __restrict__ Wl_,
          const float* __restrict__ R, const float* __restrict__ G,
          float* __restrict__ Cf,
          __nv_bfloat16* __restrict__ Ch, __nv_bfloat16* __restrict__ Cl,
          int M, int N, int K) {
    __shared__ __align__(16) __nv_bfloat16 sAh[128 * ROWB];
    __shared__ __align__(16) __nv_bfloat16 sAl[128 * ROWB];
    __shared__ __align__(16) __nv_bfloat16 sBh[128 * ROWB];
    __shared__ __align__(16) __nv_bfloat16 sBl[128 * ROWB];

    int tid  = threadIdx.x;
    int wid  = tid >> 5;
    int lane = tid & 31;
    int wr   = wid & 3;
    int wc   = wid >> 2;
    int row0 = blockIdx.y * 128;
    int col0 = blockIdx.x * 128;

    float acc[2][8][4];
    #pragma unroll
    for (int mt = 0; mt < 2; mt++)
        #pragma unroll
        for (int nt = 0; nt < 8; nt++)
            #pragma unroll
            for (int q = 0; q < 4; q++) acc[mt][nt][q] = 0.f;

    uint32_t bAh = smem_u32(sAh), bAl = smem_u32(sAl);
    uint32_t bBh = smem_u32(sBh), bBl = smem_u32(sBl);

    int aRow  = wr * 32 + (lane & 15);
    int aColB = ((lane >> 4) & 1) * 16;
    int bRow  = wc * 64 + (lane & 7) + ((lane >> 4) & 1) * 8;
    int bColB = ((lane >> 3) & 1) * 16;

    int lrow[4], lc4[4];
    #pragma unroll
    for (int i = 0; i < 4; i++) {
        int f = i * 256 + tid;
        lrow[i] = f >> 3;
        lc4[i]  = (f & 7) * 4;
    }

    uint2 pa[4], pal[4], pb[4], pbl[4];
    #pragma unroll
    for (int i = 0; i < 4; i++) {
        size_t aoff = (size_t)(row0 + lrow[i]) * K + lc4[i];
        pa[i]  = *(const uint2*)(Ah_ + aoff);
        pal[i] = *(const uint2*)(Al_ + aoff);
        int wrow = col0 + lrow[i];
        if (wrow < N) {
            size_t woff = (size_t)wrow * K + lc4[i];
            pb[i]  = *(const uint2*)(Wh_ + woff);
            pbl[i] = *(const uint2*)(Wl_ + woff);
        } else {
            pb[i] = pbl[i] = make_uint2(0u, 0u);
        }
    }

    for (int k0 = 0; k0 < K; k0 += KC) {
        #pragma unroll
        for (int i = 0; i < 4; i++) {
            int off = lrow[i] * ROWB + lc4[i];
            *(uint2*)(sAh + off) = pa[i];
            *(uint2*)(sAl + off) = pal[i];
            *(uint2*)(sBh + off) = pb[i];
            *(uint2*)(sBl + off) = pbl[i];
        }
        __syncthreads();

        if (k0 + KC < K) {
            #pragma unroll
            for (int i = 0; i < 4; i++) {
                size_t aoff = (size_t)(row0 + lrow[i]) * K + k0 + KC + lc4[i];
                pa[i]  = *(const uint2*)(Ah_ + aoff);
                pal[i] = *(const uint2*)(Al_ + aoff);
                int wrow = col0 + lrow[i];
                if (wrow < N) {
                    size_t woff = (size_t)wrow * K + k0 + KC + lc4[i];
                    pb[i]  = *(const uint2*)(Wh_ + woff);
                    pbl[i] = *(const uint2*)(Wl_ + woff);
                }
            }
        }

        #pragma unroll
        for (int ks = 0; ks < 2; ks++) {
            uint32_t Am[2][4], Al2[2][4], Bm[4][4], Bl2[4][4];
            #pragma unroll
            for (int mt = 0; mt < 2; mt++) {
                uint32_t off = (uint32_t)((aRow + mt * 16) * (ROWB * 2) + ks * 32 + aColB);
                ldsm4(Am[mt],  bAh + off);
                ldsm4(Al2[mt], bAl + off);
            }
            #pragma unroll
            for (int ntp = 0; ntp < 4; ntp++) {
                uint32_t off = (uint32_t)((bRow + ntp * 16) * (ROWB * 2) + ks * 32 + bColB);
                ldsm4(Bm[ntp],  bBh + off);
                ldsm4(Bl2[ntp], bBl + off);
            }
            #pragma unroll
            for (int mt = 0; mt < 2; mt++)
                #pragma unroll
                for (int ntp = 0; ntp < 4; ntp++) {
                    mma16816(acc[mt][ntp * 2 + 0], Am[mt], &Bm[ntp][0]);
                    mma16816(acc[mt][ntp * 2 + 1], Am[mt], &Bm[ntp][2]);
                }
            #pragma unroll
            for (int mt = 0; mt < 2; mt++)
                #pragma unroll
                for (int ntp = 0; ntp < 4; ntp++) {
                    mma16816(acc[mt][ntp * 2 + 0], Am[mt], &Bl2[ntp][0]);
                    mma16816(acc[mt][ntp * 2 + 1], Am[mt], &Bl2[ntp][2]);
                }
            #pragma unroll
            for (int mt = 0; mt < 2; mt++)
                #pragma unroll
                for (int ntp = 0; ntp < 4; ntp++) {
                    mma16816(acc[mt][ntp * 2 + 0], Al2[mt], &Bm[ntp][0]);
                    mma16816(acc[mt][ntp * 2 + 1], Al2[mt], &Bm[ntp][2]);
                }
        }
        __syncthreads();
    }

    // ---- epilogue ----
    int gid = lane >> 2;
    int tig = lane & 3;
    #pragma unroll
    for (int mt = 0; mt < 2; mt++) {
        int r0 = row0 + wr * 32 + mt * 16 + gid;
        #pragma unroll
        for (int nt = 0; nt < 8; nt++) {
            int col = col0 + wc * 64 + nt * 8 + tig * 2;
            if (col < N) {
                float2 v0 = make_float2(acc[mt][nt][0], acc[mt][nt][1]);
                float2 v1 = make_float2(acc[mt][nt][2], acc[mt][nt][3]);
                if (G) {
                    float2 g0 = *(const float2*)(G + (size_t)r0 * N + col);
                    float2 g1 = *(const float2*)(G + (size_t)(r0 + 8) * N + col);
                    v0.x = siluf(g0.x) * v0.x; v0.y = siluf(g0.y) * v0.y;
                    v1.x = siluf(g1.x) * v1.x; v1.y = siluf(g1.y) * v1.y;
                }
                if (R) {
                    float2 r0v = *(const float2*)(R + (size_t)r0 * N + col);
                    float2 r1v = *(const float2*)(R + (size_t)(r0 + 8) * N + col);
                    v0.x += r0v.x; v0.y += r0v.y;
                    v1.x += r1v.x; v1.y += r1v.y;
                }
                if (Cf) {
                    *(float2*)(Cf + (size_t)r0 * N + col)       = v0;
                    *(float2*)(Cf + (size_t)(r0 + 8) * N + col) = v1;
                } else {
                    uint32_t h0, l0;
                    split_bf16(v0.x, v0.y, h0, l0);
                    *(uint32_t*)(Ch + (size_t)r0 * N + col) = h0;
                    *(uint32_t*)(Cl + (size_t)r0 * N + col) = l0;
                    split_bf16(v1.x, v1.y, h0, l0);
                    *(uint32_t*)(Ch + (size_t)(r0 + 8) * N + col) = h0;
                    *(uint32_t*)(Cl + (size_t)(r0 + 8) * N + col) = l0;
                }
            }
        }
    }
}

// ---------------- rmsnorm over D=1024, writes split-bf16 ----------------
__global__ void __launch_bounds__(256) rmsnorm1024(const float* __restrict__ x,
                                                   const float* __restrict__ w,
                                                   __nv_bfloat16* __restrict__ oh,
                                                   __nv_bfloat16* __restrict__ ol) {
    int tok = blockIdx.x;
    int tid = threadIdx.x;
    const float4* xp = (const float4*)(x + (size_t)tok * DMODEL);
    float4 v = xp[tid];
    float ss = v.x * v.x + v.y * v.y + v.z * v.z + v.w * v.w;
    ss = blockReduceSum(ss);
    float rs = rsqrtf(ss * (1.0f / DMODEL) + EPSV);
    float4 wv = ((const float4*)w)[tid];
    float4 o;
    o.x = v.x * rs * wv.x; o.y = v.y * rs * wv.y;
    o.z = v.z * rs * wv.z; o.w = v.w * rs * wv.w;
    uint32_t h0, l0, h1, l1;
    split_bf16(o.x, o.y, h0, l0);
    split_bf16(o.z, o.w, h1, l1);
    ((uint2*)(oh + (size_t)tok * DMODEL))[tid] = make_uint2(h0, h1);
    ((uint2*)(ol + (size_t)tok * DMODEL))[tid] = make_uint2(l0, l1);
}

// ---------------- gated rmsnorm over D_INNER=2048, writes split-bf16 ----------------
__global__ void __launch_bounds__(256) gated_rmsnorm(const float* __restrict__ y,
                                                     const float* __restrict__ Z,
                                                     const float* __restrict__ w,
                                                     __nv_bfloat16* __restrict__ oh,
                                                     __nv_bfloat16* __restrict__ ol) {
    int tok = blockIdx.x;
    int tid = threadIdx.x;
    const float4* yp = (const float4*)(y + (size_t)tok * DINNER);
    const float4* zp = (const float4*)(Z + (size_t)tok * DINPROJ);
    float4 v[2];
    float ss = 0.f;
    #pragma unroll
    for (int q = 0; q < 2; q++) {
        float4 yv = yp[tid + q * 256];
        float4 zv = zp[tid + q * 256];
        float4 t;
        t.x = yv.x * siluf(zv.x); t.y = yv.y * siluf(zv.y);
        t.z = yv.z * siluf(zv.z); t.w = yv.w * siluf(zv.w);
        v[q] = t;
        ss += t.x * t.x + t.y * t.y + t.z * t.z + t.w * t.w;
    }
    ss = blockReduceSum(ss);
    float rs = rsqrtf(ss * (1.0f / DINNER) + EPSV);
    #pragma unroll
    for (int q = 0; q < 2; q++) {
        float4 wv = ((const float4*)w)[tid + q * 256];
        float4 o;
        o.x = v[q].x * rs * wv.x; o.y = v[q].y * rs * wv.y;
        o.z = v[q].z * rs * wv.z; o.w = v[q].w * rs * wv.w;
        uint32_t h0, l0, h1, l1;
        split_bf16(o.x, o.y, h0, l0);
        split_bf16(o.z, o.w, h1, l1);
        ((uint2*)(oh + (size_t)tok * DINNER))[tid + q * 256] = make_uint2(h0, h1);
        ((uint2*)(ol + (size_t)tok * DINNER))[tid + q * 256] = make_uint2(l0, l1);
    }
}

// ---------------- causal depthwise conv (width 4) + silu ----------------
__global__ void __launch_bounds__(256) conv_silu(const float* __restrict__ Z,
                                                 const float* __restrict__ cw,
                                                 const float* __restrict__ cb,
                                                 float* __restrict__ out) {
    int c   = blockIdx.x * 256 + threadIdx.x;
    int tok = blockIdx.y;
    if (c >= CONVDIM) return;
    int l = tok & (SEQLEN - 1);
    float w0 = cw[c * 4 + 0], w1 = cw[c * 4 + 1], w2 = cw[c * 4 + 2], w3 = cw[c * 4 + 3];
    const float* zc = Z + (size_t)tok * DINPROJ + DINNER + c;
    float acc = cb[c];
    acc += zc[0] * w3;
    if (l >= 1) acc += zc[-(ptrdiff_t)DINPROJ]     * w2;
    if (l >= 2) acc += zc[-(ptrdiff_t)DINPROJ * 2] * w1;
    if (l >= 3) acc += zc[-(ptrdiff_t)DINPROJ * 3] * w0;
    out[(size_t)tok * CONVDIM + c] = siluf(acc);
}

// ---------------- sequential SSM scan (restructured: 2 bars / 2 steps) ----------------
// grid 128 = (b, h, p-half); thread t owns state column n=t; hs[32] p-rows in registers.
// s_red layout [q][p][n] with 132-word rows: conflict-free scalar writes + vector reads.
__global__ void __launch_bounds__(128) ssm_scan(const float* __restrict__ xBC,
                                                const float* __restrict__ Z,
                                                const float* __restrict__ dt_bias,
                                                const float* __restrict__ A_log,
                                                const float* __restrict__ Dp,
                                                float* __restrict__ y) {
    int bid   = blockIdx.x;
    int b     = bid >> 6;
    int h     = (bid >> 1) & 31;
    int half  = bid & 1;
    int pbase = half * 32;
    int t     = threadIdx.x;

    __shared__ float s_dtx[2][2][32];
    __shared__ float s_x[2][2][32];
    __shared__ float s_partial[2][4][33];
    __shared__ __align__(16) float s_red[2][32][132];

    float hs[32];
    #pragma unroll
    for (int p = 0; p < 32; p++) hs[p] = 0.f;

    float Ahv = -__expf(A_log[h]);
    float dbh = dt_bias[h];
    float Dh  = Dp[h];
    int   p   = t & 31;
    int   j   = t >> 5;

    const float* xrow  = xBC + (size_t)b * SEQLEN * CONVDIM;
    const float* dtrow = Z + (size_t)b * SEQLEN * DINPROJ + (DINPROJ - NHEADS) + h;
    float*       yrow  = y + (size_t)b * SEQLEN * DINNER + h * HEADDIM + pbase;

    float Bv[2], Cv[2], dAc[2];
    float B1[2], C1[2], dt1[2], x1v[2];

    // prologue: pair 0 -> smem buf 0 + dAc; pair 1 -> registers
    #pragma unroll
    for (int q = 0; q < 2; q++) {
        const float* xr = xrow + (size_t)q * CONVDIM;
        Bv[q] = xr[DINNER + t];
        Cv[q] = xr[DINNER + DSTATE + t];
        float d0 = dtrow[(size_t)q * DINPROJ];
        float x0 = (t < 32) ? xr[h * HEADDIM + pbase + t] : 0.f;
        float dts = d0 + dbh;
        float dtv = (dts > 20.f) ? dts : __logf(1.f + __expf(dts));
        dAc[q] = __expf(dtv * Ahv);
        if (t < 32) { s_dtx[0][q][t] = dtv * x0; s_x[0][q][t] = x0; }
    }
    #pragma unroll
    for (int q = 0; q < 2; q++) {
        const float* xr = xrow + (size_t)(2 + q) * CONVDIM;
        B1[q]  = xr[DINNER + t];
        C1[q]  = xr[DINNER + DSTATE + t];
        dt1[q] = dtrow[(size_t)(2 + q) * DINPROJ];
        x1v[q] = (t < 32) ? xr[h * HEADDIM + pbase + t] : 0.f;
    }
    __syncthreads();

    int cur = 0;
    for (int i = 0; i < SEQLEN / 2; i++) {
        int nxt = cur ^ 1;
        float dAn[2] = {0.f, 0.f};
        // prepare pair i+1: dtx/x into other buffer, dA into regs
        if (i < SEQLEN / 2 - 1) {
            #pragma unroll
            for (int q = 0; q < 2; q++) {
                float dts = dt1[q] + dbh;
                float dtv = (dts > 20.f) ? dts : __logf(1.f + __expf(dts));
                dAn[q] = __expf(dtv * Ahv);
                if (t < 32) { s_dtx[nxt][q][t] = dtv * x1v[q]; s_x[nxt][q][t] = x1v[q]; }
            }
        }
        // state update + per-(p,n) contributions
        #pragma unroll
        for (int q = 0; q < 2; q++) {
            float dAq = dAc[q], Bq = Bv[q], Cq = Cv[q];
            #pragma unroll
            for (int pp = 0; pp < 32; pp += 4) {
                float4 d4 = *(const float4*)&s_dtx[cur][q][pp];
                hs[pp + 0] = fmaf(hs[pp + 0], dAq, d4.x * Bq);
                hs[pp + 1] = fmaf(hs[pp + 1], dAq, d4.y * Bq);
                hs[pp + 2] = fmaf(hs[pp + 2], dAq, d4.z * Bq);
                hs[pp + 3] = fmaf(hs[pp + 3], dAq, d4.w * Bq);
                s_red[q][pp + 0][t] = hs[pp + 0] * Cq;
                s_red[q][pp + 1][t] = hs[pp + 1] * Cq;
                s_red[q][pp + 2][t] = hs[pp + 2] * Cq;
                s_red[q][pp + 3][t] = hs[pp + 3] * Cq;
            }
        }
        __syncthreads();

        // tree-reduce over n: thread (p, j) sums 32 columns via 8 vector loads
        #pragma unroll
        for (int q = 0; q < 2; q++) {
            const float4* rp = (const float4*)&s_red[q][p][j * 32];
            float4 a0 = rp[0], a1 = rp[1], a2 = rp[2], a3 = rp[3];
            float4 a4 = rp[4], a5 = rp[5], a6 = rp[6], a7 = rp[7];
            a0.x += a1.x; a0.y += a1.y; a0.z += a1.z; a0.w += a1.w;
            a2.x += a3.x; a2.y += a3.y; a2.z += a3.z; a2.w += a3.w;
            a4.x += a5.x; a4.y += a5.y; a4.z += a5.z; a4.w += a5.w;
            a6.x += a7.x; a6.y += a7.y; a6.z += a7.z; a6.w += a7.w;
            a0.x += a2.x; a0.y += a2.y; a0.z += a2.z; a0.w += a2.w;
            a4.x += a6.x; a4.y += a6.y; a4.z += a6.z; a4.w += a6.w;
            a0.x += a4.x; a0.y += a4.y; a0.z += a4.z; a0.w += a4.w;
            s_partial[q][j][p] = (a0.x + a0.y) + (a0.z + a0.w);
        }
        __syncthreads();

        if (t < 32) {
            #pragma unroll
            for (int q = 0; q < 2; q++) {
                float yv = s_partial[q][0][t] + s_partial[q][1][t]
                         + s_partial[q][2][t] + s_partial[q][3][t];
                yrow[(size_t)(2 * i + q) * DINNER + t] = yv + Dh * s_x[cur][q][t];
            }
        }

        // shift pair regs, prefetch pair i+2
        dAc[0] = dAn[0]; dAc[1] = dAn[1];
        Bv[0] = B1[0]; Bv[1] = B1[1];
        Cv[0] = C1[0]; Cv[1] = C1[1];
        if (i < SEQLEN / 2 - 2) {
            #pragma unroll
            for (int q = 0; q < 2; q++) {
                int s = 2 * i + 4 + q;
                const float* xr = xrow + (size_t)s * CONVDIM;
                B1[q]  = xr[DINNER + t];
                C1[q]  = xr[DINNER + DSTATE + t];
                dt1[q] = dtrow[(size_t)s * DINPROJ];
                x1v[q] = (t < 32) ? xr[h * HEADDIM + pbase + t] : 0.f;
            }
        }
        cur = nxt;
    }
}

// ---------------- launch ----------------
extern "C" void kernel_launch(void* const* d_in, const int* in_sizes, int n_in,
                              void* d_out, int out_size) {
    const float* hidden     = (const float*)d_in[0];
    const float* norm_w     = (const float*)d_in[1];
    const float* in_proj_w  = (const float*)d_in[2];
    const float* conv_w     = (const float*)d_in[3];
    const float* conv_b     = (const float*)d_in[4];
    const float* dt_bias    = (const float*)d_in[5];
    const float* A_log      = (const float*)d_in[6];
    const float* Dvec       = (const float*)d_in[7];
    const float* ssm_norm_w = (const float*)d_in[8];
    const float* out_proj_w = (const float*)d_in[9];
    const float* post_norm_w= (const float*)d_in[10];
    const float* gate_w     = (const float*)d_in[11];
    const float* up_w       = (const float*)d_in[12];
    const float* down_w     = (const float*)d_in[13];
    float* out = (float*)d_out;

    float *Z, *xBC, *y, *x2, *gg;
    cudaGetSymbolAddress((void**)&Z,   g_Z);
    cudaGetSymbolAddress((void**)&xBC, g_xBC);
    cudaGetSymbolAddress((void**)&y,   g_y);
    cudaGetSymbolAddress((void**)&x2,  g_x2);
    cudaGetSymbolAddress((void**)&gg,  g_g);

    __nv_bfloat16 *x1h, *x1l, *h2h, *h2l, *y2h, *y2l, *ddh, *ddl;
    cudaGetSymbolAddress((void**)&x1h, g_x1h); cudaGetSymbolAddress((void**)&x1l, g_x1l);
    cudaGetSymbolAddress((void**)&h2h, g_h2h); cudaGetSymbolAddress((void**)&h2l, g_h2l);
    cudaGetSymbolAddress((void**)&y2h, g_y2h); cudaGetSymbolAddress((void**)&y2l, g_y2l);
    cudaGetSymbolAddress((void**)&ddh, g_ddh); cudaGetSymbolAddress((void**)&ddl, g_ddl);

    __nv_bfloat16 *wih, *wil, *woh, *wol, *wgh, *wgl, *wuh, *wul, *wdh, *wdl;
    cudaGetSymbolAddress((void**)&wih, g_wih); cudaGetSymbolAddress((void**)&wil, g_wil);
    cudaGetSymbolAddress((void**)&woh, g_woh); cudaGetSymbolAddress((void**)&wol, g_wol);
    cudaGetSymbolAddress((void**)&wgh, g_wgh); cudaGetSymbolAddress((void**)&wgl, g_wgl);
    cudaGetSymbolAddress((void**)&wuh, g_wuh); cudaGetSymbolAddress((void**)&wul, g_wul);
    cudaGetSymbolAddress((void**)&wdh, g_wdh); cudaGetSymbolAddress((void**)&wdl, g_wdl);

    // 0. weight pre-conversion to split-bf16
    {
        int n;
        n = DINPROJ * DMODEL / 4; f32_split<<<(n + 255) / 256, 256>>>(in_proj_w,  wih, wil, n);
        n = DMODEL * DINNER / 4;  f32_split<<<(n + 255) / 256, 256>>>(out_proj_w, woh, wol, n);
        n = INTERD * DMODEL / 4;  f32_split<<<(n + 255) / 256, 256>>>(gate_w,     wgh, wgl, n);
        n = INTERD * DMODEL / 4;  f32_split<<<(n + 255) / 256, 256>>>(up_w,       wuh, wul, n);
        n = DMODEL * INTERD / 4;  f32_split<<<(n + 255) / 256, 256>>>(down_w,     wdh, wdl, n);
    }

    // 1. pre-norm (writes split-bf16)
    rmsnorm1024<<<NTOK, 256>>>(hidden, norm_w, x1h, x1l);
    // 2. in_proj: Z = x1 @ in_proj_w^T (fp32 out)
    gemm_bf16<<<dim3((DINPROJ + 127) / 128, NTOK / 128), 256>>>(
        x1h, x1l, wih, wil, nullptr, nullptr, Z, nullptr, nullptr, NTOK, DINPROJ, DMODEL);
    // 3. causal conv + silu
    conv_silu<<<dim3((CONVDIM + 255) / 256, NTOK), 256>>>(Z, conv_w, conv_b, xBC);
    // 4. sequential SSM scan (+ D skip)
    ssm_scan<<<128, 128>>>(xBC, Z, dt_bias, A_log, Dvec, y);
    // 5. gated rmsnorm (writes split-bf16)
    gated_rmsnorm<<<NTOK, 256>>>(y, Z, ssm_norm_w, y2h, y2l);
    // 6. out_proj + residual (fp32 out)
    gemm_bf16<<<dim3(DMODEL / 128, NTOK / 128), 256>>>(
        y2h, y2l, woh, wol, hidden, nullptr, x2, nullptr, nullptr, NTOK, DMODEL, DINNER);
    // 7. post-norm (writes split-bf16)
    rmsnorm1024<<<NTOK, 256>>>(x2, post_norm_w, h2h, h2l);
    // 8. MLP gate (fp32 out)
    gemm_bf16<<<dim3((INTERD + 127) / 128, NTOK / 128), 256>>>(
        h2h, h2l, wgh, wgl, nullptr, nullptr, gg, nullptr, nullptr, NTOK, INTERD, DMODEL);
    // 9. MLP up, fused swiglu epilogue: dd = silu(gg)*acc (split-bf16 out)
    gemm_bf16<<<dim3((INTERD + 127) / 128, NTOK / 128), 256>>>(
        h2h, h2l, wuh, wul, nullptr, gg, nullptr, ddh, ddl, NTOK, INTERD, DMODEL);
    // 10. down proj + residual -> out
    gemm_bf16<<<dim3(DMODEL / 128, NTOK / 128), 256>>>(
        ddh, ddl, wdh, wdl, x2, nullptr, out, nullptr, nullptr, NTOK, DMODEL, INTERD);
}

// round 5
// speedup vs baseline: 2.1478x; 1.1328x over previous
#include <cuda_runtime.h>
#include <cuda_bf16.h>
#include <cstdint>
#include <math.h>

// ---------------- problem constants ----------------
#define BATCH   2
#define SEQLEN  1024
#define DMODEL  1024
#define DSTATE  128
#define DCONV   4
#define HEADDIM 64
#define DINNER  2048
#define NHEADS  32
#define CONVDIM 2304     // DINNER + 2*DSTATE
#define DINPROJ 4384     // 2*DINNER + 2*DSTATE + NHEADS
#define INTERD  2752
#define NTOK    2048     // BATCH*SEQLEN
#define EPSV    1e-6f

// ---------------- fp32 scratch ----------------
__device__ float g_Z  [NTOK * DINPROJ];
__device__ float g_xBC[NTOK * CONVDIM];
__device__ float g_y  [NTOK * DINNER];
__device__ float g_x2 [NTOK * DMODEL];
__device__ float g_g  [NTOK * INTERD];

// ---------------- split-bf16 activations ----------------
__device__ __nv_bfloat16 g_x1h[NTOK * DMODEL], g_x1l[NTOK * DMODEL];
__device__ __nv_bfloat16 g_h2h[NTOK * DMODEL], g_h2l[NTOK * DMODEL];
__device__ __nv_bfloat16 g_y2h[NTOK * DINNER], g_y2l[NTOK * DINNER];
__device__ __nv_bfloat16 g_ddh[NTOK * INTERD], g_ddl[NTOK * INTERD];

// ---------------- split-bf16 weights ----------------
__device__ __nv_bfloat16 g_wih[DINPROJ * DMODEL], g_wil[DINPROJ * DMODEL];
__device__ __nv_bfloat16 g_woh[DMODEL * DINNER],  g_wol[DMODEL * DINNER];
__device__ __nv_bfloat16 g_wgh[INTERD * DMODEL],  g_wgl[INTERD * DMODEL];
__device__ __nv_bfloat16 g_wuh[INTERD * DMODEL],  g_wul[INTERD * DMODEL];
__device__ __nv_bfloat16 g_wdh[DMODEL * INTERD],  g_wdl[DMODEL * INTERD];

// ---------------- helpers ----------------
__device__ __forceinline__ uint32_t smem_u32(const void* p) {
    uint32_t a;
    asm("{ .reg .u64 t; cvta.to.shared.u64 t, %1; cvt.u32.u64 %0, t; }" : "=r"(a) : "l"(p));
    return a;
}
__device__ __forceinline__ float blockReduceSum(float v) {
    __shared__ float sb[32];
    int lane = threadIdx.x & 31;
    int w    = threadIdx.x >> 5;
    #pragma unroll
    for (int o = 16; o; o >>= 1) v += __shfl_xor_sync(0xffffffffu, v, o);
    if (lane == 0) sb[w] = v;
    __syncthreads();
    int nw = blockDim.x >> 5;
    float r = (threadIdx.x < (unsigned)nw) ? sb[threadIdx.x] : 0.f;
    if (w == 0) {
        #pragma unroll
        for (int o = 16; o; o >>= 1) r += __shfl_xor_sync(0xffffffffu, r, o);
        if (lane == 0) sb[0] = r;
    }
    __syncthreads();
    return sb[0];
}
__device__ __forceinline__ float siluf(float x) { return x * (1.0f / (1.0f + __expf(-x))); }

__device__ __forceinline__ void ldsm4(uint32_t* r, uint32_t addr) {
    asm volatile("ldmatrix.sync.aligned.m8n8.x4.shared.b16 {%0,%1,%2,%3}, [%4];"
                 : "=r"(r[0]), "=r"(r[1]), "=r"(r[2]), "=r"(r[3]) : "r"(addr));
}
__device__ __forceinline__ void mma16816(float* d, const uint32_t* a, const uint32_t* b) {
    asm volatile(
        "mma.sync.aligned.m16n8k16.row.col.f32.bf16.bf16.f32 "
        "{%0,%1,%2,%3}, {%4,%5,%6,%7}, {%8,%9}, {%0,%1,%2,%3};"
        : "+f"(d[0]), "+f"(d[1]), "+f"(d[2]), "+f"(d[3])
        : "r"(a[0]), "r"(a[1]), "r"(a[2]), "r"(a[3]), "r"(b[0]), "r"(b[1]));
}
__device__ __forceinline__ void split_bf16(float a, float b, uint32_t& hi, uint32_t& lo) {
    __nv_bfloat16 ha = __float2bfloat16(a), hb = __float2bfloat16(b);
    __nv_bfloat16 la = __float2bfloat16(a - __bfloat162float(ha));
    __nv_bfloat16 lb = __float2bfloat16(b - __bfloat162float(hb));
    __nv_bfloat162 th(ha, hb), tl(la, lb);
    hi = *reinterpret_cast<uint32_t*>(&th);
    lo = *reinterpret_cast<uint32_t*>(&tl);
}
__device__ __forceinline__ void cp_async16(uint32_t dst, const void* src, int src_bytes) {
    asm volatile("cp.async.cg.shared.global [%0], [%1], 16, %2;"
                 :: "r"(dst), "l"(src), "r"(src_bytes));
}
__device__ __forceinline__ void cp_commit() { asm volatile("cp.async.commit_group;" ::: "memory"); }
__device__ __forceinline__ void cp_wait0()  { asm volatile("cp.async.wait_group 0;" ::: "memory"); }
__device__ __forceinline__ void cp_wait1()  { asm volatile("cp.async.wait_group 1;" ::: "memory"); }

// ---------------- fp32 -> split-bf16 converter ----------------
__global__ void __launch_bounds__(256) f32_split(const float* __restrict__ in,
                                                 __nv_bfloat16* __restrict__ oh,
                                                 __nv_bfloat16* __restrict__ ol, int n4) {
    int i = blockIdx.x * 256 + threadIdx.x;
    if (i < n4) {
        float4 v = ((const float4*)in)[i];
        uint32_t h0, l0, h1, l1;
        split_bf16(v.x, v.y, h0, l0);
        split_bf16(v.z, v.w, h1, l1);
        ((uint2*)oh)[i] = make_uint2(h0, h1);
        ((uint2*)ol)[i] = make_uint2(l0, l1);
    }
}

// ================= split-bf16 tensor-core GEMM: cp.async double-buffered =================
// C[M,N] = (Ah+Al)[M,K] @ (Wh+Wl)[N,K]^T via AhBh + AhBl + AlBh.
#define KC 32
#define ROWB 40
#define STAGE_ELEMS (128 * ROWB)        // per array (bf16)
#define STAGE_BYTES (4 * STAGE_ELEMS * 2)  // 4 arrays per stage = 40960 B
#define GEMM_SMEM (2 * STAGE_BYTES)        // 81920 B

extern __shared__ __align__(16) __nv_bfloat16 dsm[];

__global__ void __launch_bounds__(256, 2)
gemm_bf16(const __nv_bfloat16* __restrict__ Ah_, const __nv_bfloat16* __restrict__ Al_,
          const __nv_bfloat16* __restrict__ Wh_, const __nv_bfloat16* __restrict__ Wl_,
          const float* __restrict__ R, const float* __restrict__ G,
          float* __restrict__ Cf,
          __nv_bfloat16* __restrict__ Ch, __nv_bfloat16* __restrict__ Cl,
          int M, int N, int K) {
    uint32_t sbase = smem_u32(dsm);
    int tid  = threadIdx.x;
    int wid  = tid >> 5;
    int lane = tid & 31;
    int wr   = wid & 3;
    int wc   = wid >> 2;
    int row0 = blockIdx.y * 128;
    int col0 = blockIdx.x * 128;

    float acc[2][8][4];
    #pragma unroll
    for (int mt = 0; mt < 2; mt++)
        #pragma unroll
        for (int nt = 0; nt < 8; nt++)
            #pragma unroll
            for (int q = 0; q < 4; q++) acc[mt][nt][q] = 0.f;

    // ldmatrix lane address components (bytes within a stage array)
    int aRow  = wr * 32 + (lane & 15);
    int aColB = ((lane >> 4) & 1) * 16;
    int bRow  = wc * 64 + (lane & 7) + ((lane >> 4) & 1) * 8;
    int bColB = ((lane >> 3) & 1) * 16;

    // cp.async slots: 2 × 16B per array per thread per chunk
    int rowL[2], ceL[2];
    #pragma unroll
    for (int s = 0; s < 2; s++) {
        int idx = s * 256 + tid;
        rowL[s] = idx >> 2;          // 0..127
        ceL[s]  = (idx & 3) * 8;     // bf16 element offset 0/8/16/24
    }
    int wrow0 = col0 + rowL[0], wrow1 = col0 + rowL[1];
    int sz0 = (wrow0 < N) ? 16 : 0, sz1 = (wrow1 < N) ? 16 : 0;
    int wsafe0 = (wrow0 < N) ? wrow0 : 0, wsafe1 = (wrow1 < N) ? wrow1 : 0;

    int NC = K / KC;

    // issue copy of chunk c into stage st
    auto issue = [&](int c, int st) {
        uint32_t base = sbase + st * STAGE_BYTES;
        #pragma unroll
        for (int s = 0; s < 2; s++) {
            int row = rowL[s], ce = ceL[s];
            uint32_t doff = (uint32_t)(row * ROWB + ce) * 2;
            size_t goA = (size_t)(row0 + row) * K + c * KC + ce;
            cp_async16(base + doff,                       Ah_ + goA, 16);
            cp_async16(base + STAGE_ELEMS * 2 + doff,     Al_ + goA, 16);
            size_t goW = (size_t)(s ? wsafe1 : wsafe0) * K + c * KC + ce;
            int sz = s ? sz1 : sz0;
            cp_async16(base + STAGE_ELEMS * 4 + doff,     Wh_ + goW, sz);
            cp_async16(base + STAGE_ELEMS * 6 + doff,     Wl_ + goW, sz);
        }
    };

    issue(0, 0);
    cp_commit();

    for (int c = 0; c < NC; c++) {
        if (c + 1 < NC) { issue(c + 1, (c + 1) & 1); cp_commit(); cp_wait1(); }
        else            { cp_wait0(); }
        __syncthreads();

        uint32_t base   = sbase + (c & 1) * STAGE_BYTES;
        uint32_t alBase = base + STAGE_ELEMS * 2;
        uint32_t bhBase = base + STAGE_ELEMS * 4;
        uint32_t blBase = base + STAGE_ELEMS * 6;

        #pragma unroll
        for (int ks = 0; ks < 2; ks++) {
            uint32_t Am[2][4], Al2[2][4];
            #pragma unroll
            for (int mt = 0; mt < 2; mt++) {
                uint32_t off = (uint32_t)((aRow + mt * 16) * (ROWB * 2) + ks * 32 + aColB);
                ldsm4(Am[mt],  base   + off);
                ldsm4(Al2[mt], alBase + off);
            }
            #pragma unroll
            for (int ntp = 0; ntp < 4; ntp++) {
                uint32_t Bm[4], Bl2[4];
                uint32_t off = (uint32_t)((bRow + ntp * 16) * (ROWB * 2) + ks * 32 + bColB);
                ldsm4(Bm,  bhBase + off);
                ldsm4(Bl2, blBase + off);
                #pragma unroll
                for (int mt = 0; mt < 2; mt++) {
                    mma16816(acc[mt][ntp * 2 + 0], Am[mt], &Bm[0]);
                    mma16816(acc[mt][ntp * 2 + 1], Am[mt], &Bm[2]);
                }
                #pragma unroll
                for (int mt = 0; mt < 2; mt++) {
                    mma16816(acc[mt][ntp * 2 + 0], Am[mt], &Bl2[0]);
                    mma16816(acc[mt][ntp * 2 + 1], Am[mt], &Bl2[2]);
                }
                #pragma unroll
                for (int mt = 0; mt < 2; mt++) {
                    mma16816(acc[mt][ntp * 2 + 0], Al2[mt], &Bm[0]);
                    mma16816(acc[mt][ntp * 2 + 1], Al2[mt], &Bm[2]);
                }
            }
        }
        __syncthreads();
    }

    // ---- epilogue ----
    int gid = lane >> 2;
    int tig = lane & 3;
    #pragma unroll
    for (int mt = 0; mt < 2; mt++) {
        int r0 = row0 + wr * 32 + mt * 16 + gid;
        #pragma unroll
        for (int nt = 0; nt < 8; nt++) {
            int col = col0 + wc * 64 + nt * 8 + tig * 2;
            if (col < N) {
                float2 v0 = make_float2(acc[mt][nt][0], acc[mt][nt][1]);
                float2 v1 = make_float2(acc[mt][nt][2], acc[mt][nt][3]);
                if (G) {
                    float2 g0 = *(const float2*)(G + (size_t)r0 * N + col);
                    float2 g1 = *(const float2*)(G + (size_t)(r0 + 8) * N + col);
                    v0.x = siluf(g0.x) * v0.x; v0.y = siluf(g0.y) * v0.y;
                    v1.x = siluf(g1.x) * v1.x; v1.y = siluf(g1.y) * v1.y;
                }
                if (R) {
                    float2 r0v = *(const float2*)(R + (size_t)r0 * N + col);
                    float2 r1v = *(const float2*)(R + (size_t)(r0 + 8) * N + col);
                    v0.x += r0v.x; v0.y += r0v.y;
                    v1.x += r1v.x; v1.y += r1v.y;
                }
                if (Cf) {
                    *(float2*)(Cf + (size_t)r0 * N + col)       = v0;
                    *(float2*)(Cf + (size_t)(r0 + 8) * N + col) = v1;
                } else {
                    uint32_t h0, l0;
                    split_bf16(v0.x, v0.y, h0, l0);
                    *(uint32_t*)(Ch + (size_t)r0 * N + col) = h0;
                    *(uint32_t*)(Cl + (size_t)r0 * N + col) = l0;
                    split_bf16(v1.x, v1.y, h0, l0);
                    *(uint32_t*)(Ch + (size_t)(r0 + 8) * N + col) = h0;
                    *(uint32_t*)(Cl + (size_t)(r0 + 8) * N + col) = l0;
                }
            }
        }
    }
}

// ---------------- rmsnorm over D=1024, writes split-bf16 ----------------
__global__ void __launch_bounds__(256) rmsnorm1024(const float* __restrict__ x,
                                                   const float* __restrict__ w,
                                                   __nv_bfloat16* __restrict__ oh,
                                                   __nv_bfloat16* __restrict__ ol) {
    int tok = blockIdx.x;
    int tid = threadIdx.x;
    const float4* xp = (const float4*)(x + (size_t)tok * DMODEL);
    float4 v = xp[tid];
    float ss = v.x * v.x + v.y * v.y + v.z * v.z + v.w * v.w;
    ss = blockReduceSum(ss);
    float rs = rsqrtf(ss * (1.0f / DMODEL) + EPSV);
    float4 wv = ((const float4*)w)[tid];
    float4 o;
    o.x = v.x * rs * wv.x; o.y = v.y * rs * wv.y;
    o.z = v.z * rs * wv.z; o.w = v.w * rs * wv.w;
    uint32_t h0, l0, h1, l1;
    split_bf16(o.x, o.y, h0, l0);
    split_bf16(o.z, o.w, h1, l1);
    ((uint2*)(oh + (size_t)tok * DMODEL))[tid] = make_uint2(h0, h1);
    ((uint2*)(ol + (size_t)tok * DMODEL))[tid] = make_uint2(l0, l1);
}

// ---------------- gated rmsnorm over D_INNER=2048, writes split-bf16 ----------------
__global__ void __launch_bounds__(256) gated_rmsnorm(const float* __restrict__ y,
                                                     const float* __restrict__ Z,
                                                     const float* __restrict__ w,
                                                     __nv_bfloat16* __restrict__ oh,
                                                     __nv_bfloat16* __restrict__ ol) {
    int tok = blockIdx.x;
    int tid = threadIdx.x;
    const float4* yp = (const float4*)(y + (size_t)tok * DINNER);
    const float4* zp = (const float4*)(Z + (size_t)tok * DINPROJ);
    float4 v[2];
    float ss = 0.f;
    #pragma unroll
    for (int q = 0; q < 2; q++) {
        float4 yv = yp[tid + q * 256];
        float4 zv = zp[tid + q * 256];
        float4 t;
        t.x = yv.x * siluf(zv.x); t.y = yv.y * siluf(zv.y);
        t.z = yv.z * siluf(zv.z); t.w = yv.w * siluf(zv.w);
        v[q] = t;
        ss += t.x * t.x + t.y * t.y + t.z * t.z + t.w * t.w;
    }
    ss = blockReduceSum(ss);
    float rs = rsqrtf(ss * (1.0f / DINNER) + EPSV);
    #pragma unroll
    for (int q = 0; q < 2; q++) {
        float4 wv = ((const float4*)w)[tid + q * 256];
        float4 o;
        o.x = v[q].x * rs * wv.x; o.y = v[q].y * rs * wv.y;
        o.z = v[q].z * rs * wv.z; o.w = v[q].w * rs * wv.w;
        uint32_t h0, l0, h1, l1;
        split_bf16(o.x, o.y, h0, l0);
        split_bf16(o.z, o.w, h1, l1);
        ((uint2*)(oh + (size_t)tok * DINNER))[tid + q * 256] = make_uint2(h0, h1);
        ((uint2*)(ol + (size_t)tok * DINNER))[tid + q * 256] = make_uint2(l0, l1);
    }
}

// ---------------- causal depthwise conv (width 4) + silu ----------------
__global__ void __launch_bounds__(256) conv_silu(const float* __restrict__ Z,
                                                 const float* __restrict__ cw,
                                                 const float* __restrict__ cb,
                                                 float* __restrict__ out) {
    int c   = blockIdx.x * 256 + threadIdx.x;
    int tok = blockIdx.y;
    if (c >= CONVDIM) return;
    int l = tok & (SEQLEN - 1);
    float w0 = cw[c * 4 + 0], w1 = cw[c * 4 + 1], w2 = cw[c * 4 + 2], w3 = cw[c * 4 + 3];
    const float* zc = Z + (size_t)tok * DINPROJ + DINNER + c;
    float acc = cb[c];
    acc += zc[0] * w3;
    if (l >= 1) acc += zc[-(ptrdiff_t)DINPROJ]     * w2;
    if (l >= 2) acc += zc[-(ptrdiff_t)DINPROJ * 2] * w1;
    if (l >= 3) acc += zc[-(ptrdiff_t)DINPROJ * 3] * w0;
    out[(size_t)tok * CONVDIM + c] = siluf(acc);
}

// ---------------- sequential SSM scan: 8-way p-split, 512 blocks ----------------
// block = (b, h, oct): owns 8 p-rows. 128 threads, thread t owns state column n=t.
// s_red row stride 144 (mod 32 == 16) -> the two p-rows of a warp hit disjoint bank halves.
__global__ void __launch_bounds__(128) ssm_scan(const float* __restrict__ xBC,
                                                const float* __restrict__ Z,
                                                const float* __restrict__ dt_bias,
                                                const float* __restrict__ A_log,
                                                const float* __restrict__ Dp,
                                                float* __restrict__ y) {
    int bid   = blockIdx.x;          // 512 = b(2) * h(32) * oct(8)
    int b     = bid >> 8;
    int h     = (bid >> 3) & 31;
    int oct   = bid & 7;
    int pbase = oct * 8;
    int t     = threadIdx.x;

    __shared__ float s_dtx[2][2][8];
    __shared__ float s_x[2][2][8];
    __shared__ float s_red[2][8][144];

    float hs[8];
    #pragma unroll
    for (int p = 0; p < 8; p++) hs[p] = 0.f;

    float Ahv = -__expf(A_log[h]);
    float dbh = dt_bias[h];
    float Dh  = Dp[h];
    int   rp  = t >> 4;   // reduction row 0..7
    int   ri  = t & 15;   // reduction lane within row

    const float* xrow  = xBC + (size_t)b * SEQLEN * CONVDIM;
    const float* dtrow = Z + (size_t)b * SEQLEN * DINPROJ + (DINPROJ - NHEADS) + h;
    float*       yrow  = y + (size_t)b * SEQLEN * DINNER + h * HEADDIM + pbase;

    float Bv[2], Cv[2], dAc[2];
    float B1[2], C1[2], dt1[2], x1v[2];

    // prologue: pair 0 -> smem buf 0 + dAc regs; pair 1 -> registers
    #pragma unroll
    for (int q = 0; q < 2; q++) {
        const float* xr = xrow + (size_t)q * CONVDIM;
        Bv[q] = xr[DINNER + t];
        Cv[q] = xr[DINNER + DSTATE + t];
        float dts = dtrow[(size_t)q * DINPROJ] + dbh;
        float dtv = (dts > 20.f) ? dts : __logf(1.f + __expf(dts));
        dAc[q] = __expf(dtv * Ahv);
        if (t < 8) {
            float x0 = xr[h * HEADDIM + pbase + t];
            s_dtx[0][q][t] = dtv * x0; s_x[0][q][t] = x0;
        }
    }
    #pragma unroll
    for (int q = 0; q < 2; q++) {
        const float* xr = xrow + (size_t)(2 + q) * CONVDIM;
        B1[q]  = xr[DINNER + t];
        C1[q]  = xr[DINNER + DSTATE + t];
        dt1[q] = dtrow[(size_t)(2 + q) * DINPROJ];
        x1v[q] = (t < 8) ? xr[h * HEADDIM + pbase + t] : 0.f;
    }
    __syncthreads();

    int cur = 0;
    for (int i = 0; i < SEQLEN / 2; i++) {
        int nxt = cur ^ 1;
        float dAn[2] = {0.f, 0.f};
        // phase A: prepare pair i+1 into other buffer
        if (i < SEQLEN / 2 - 1) {
            #pragma unroll
            for (int q = 0; q < 2; q++) {
                float dts = dt1[q] + dbh;
                float dtv = (dts > 20.f) ? dts : __logf(1.f + __expf(dts));
                dAn[q] = __expf(dtv * Ahv);
                if (t < 8) { s_dtx[nxt][q][t] = dtv * x1v[q]; s_x[nxt][q][t] = x1v[q]; }
            }
        }
        // phase B: state update + per-(p,n) contributions
        #pragma unroll
        for (int q = 0; q < 2; q++) {
            float dAq = dAc[q], Bq = Bv[q], Cq = Cv[q];
            #pragma unroll
            for (int p = 0; p < 8; p++) {
                hs[p] = fmaf(hs[p], dAq, s_dtx[cur][q][p] * Bq);
                s_red[q][p][t] = hs[p] * Cq;
            }
        }
        __syncthreads();

        // phase C: reduce over n (16 threads per p-row, then width-16 shfl tree)
        #pragma unroll
        for (int q = 0; q < 2; q++) {
            float sum = 0.f;
            #pragma unroll
            for (int k = 0; k < 8; k++) sum += s_red[q][rp][k * 16 + ri];
            #pragma unroll
            for (int o = 8; o; o >>= 1) sum += __shfl_xor_sync(0xffffffffu, sum, o, 16);
            if (ri == 0)
                yrow[(size_t)(2 * i + q) * DINNER + rp] = sum + Dh * s_x[cur][q][rp];
        }

        // shift regs, prefetch pair i+2
        dAc[0] = dAn[0]; dAc[1] = dAn[1];
        Bv[0] = B1[0]; Bv[1] = B1[1];
        Cv[0] = C1[0]; Cv[1] = C1[1];
        if (i < SEQLEN / 2 - 2) {
            #pragma unroll
            for (int q = 0; q < 2; q++) {
                int s = 2 * i + 4 + q;
                const float* xr = xrow + (size_t)s * CONVDIM;
                B1[q]  = xr[DINNER + t];
                C1[q]  = xr[DINNER + DSTATE + t];
                dt1[q] = dtrow[(size_t)s * DINPROJ];
                x1v[q] = (t < 8) ? xr[h * HEADDIM + pbase + t] : 0.f;
            }
        }
        __syncthreads();   // s_red / s_dtx[cur] reads done before next iter rewrites
        cur = nxt;
    }
}

// ---------------- launch ----------------
extern "C" void kernel_launch(void* const* d_in, const int* in_sizes, int n_in,
                              void* d_out, int out_size) {
    const float* hidden     = (const float*)d_in[0];
    const float* norm_w     = (const float*)d_in[1];
    const float* in_proj_w  = (const float*)d_in[2];
    const float* conv_w     = (const float*)d_in[3];
    const float* conv_b     = (const float*)d_in[4];
    const float* dt_bias    = (const float*)d_in[5];
    const float* A_log      = (const float*)d_in[6];
    const float* Dvec       = (const float*)d_in[7];
    const float* ssm_norm_w = (const float*)d_in[8];
    const float* out_proj_w = (const float*)d_in[9];
    const float* post_norm_w= (const float*)d_in[10];
    const float* gate_w     = (const float*)d_in[11];
    const float* up_w       = (const float*)d_in[12];
    const float* down_w     = (const float*)d_in[13];
    float* out = (float*)d_out;

    float *Z, *xBC, *y, *x2, *gg;
    cudaGetSymbolAddress((void**)&Z,   g_Z);
    cudaGetSymbolAddress((void**)&xBC, g_xBC);
    cudaGetSymbolAddress((void**)&y,   g_y);
    cudaGetSymbolAddress((void**)&x2,  g_x2);
    cudaGetSymbolAddress((void**)&gg,  g_g);

    __nv_bfloat16 *x1h, *x1l, *h2h, *h2l, *y2h, *y2l, *ddh, *ddl;
    cudaGetSymbolAddress((void**)&x1h, g_x1h); cudaGetSymbolAddress((void**)&x1l, g_x1l);
    cudaGetSymbolAddress((void**)&h2h, g_h2h); cudaGetSymbolAddress((void**)&h2l, g_h2l);
    cudaGetSymbolAddress((void**)&y2h, g_y2h); cudaGetSymbolAddress((void**)&y2l, g_y2l);
    cudaGetSymbolAddress((void**)&ddh, g_ddh); cudaGetSymbolAddress((void**)&ddl, g_ddl);

    __nv_bfloat16 *wih, *wil, *woh, *wol, *wgh, *wgl, *wuh, *wul, *wdh, *wdl;
    cudaGetSymbolAddress((void**)&wih, g_wih); cudaGetSymbolAddress((void**)&wil, g_wil);
    cudaGetSymbolAddress((void**)&woh, g_woh); cudaGetSymbolAddress((void**)&wol, g_wol);
    cudaGetSymbolAddress((void**)&wgh, g_wgh); cudaGetSymbolAddress((void**)&wgl, g_wgl);
    cudaGetSymbolAddress((void**)&wuh, g_wuh); cudaGetSymbolAddress((void**)&wul, g_wul);
    cudaGetSymbolAddress((void**)&wdh, g_wdh); cudaGetSymbolAddress((void**)&wdl, g_wdl);

    cudaFuncSetAttribute(gemm_bf16, cudaFuncAttributeMaxDynamicSharedMemorySize, GEMM_SMEM);

    // 0. weight pre-conversion to split-bf16
    {
        int n;
        n = DINPROJ * DMODEL / 4; f32_split<<<(n + 255) / 256, 256>>>(in_proj_w,  wih, wil, n);
        n = DMODEL * DINNER / 4;  f32_split<<<(n + 255) / 256, 256>>>(out_proj_w, woh, wol, n);
        n = INTERD * DMODEL / 4;  f32_split<<<(n + 255) / 256, 256>>>(gate_w,     wgh, wgl, n);
        n = INTERD * DMODEL / 4;  f32_split<<<(n + 255) / 256, 256>>>(up_w,       wuh, wul, n);
        n = DMODEL * INTERD / 4;  f32_split<<<(n + 255) / 256, 256>>>(down_w,     wdh, wdl, n);
    }

    // 1. pre-norm (writes split-bf16)
    rmsnorm1024<<<NTOK, 256>>>(hidden, norm_w, x1h, x1l);
    // 2. in_proj
    gemm_bf16<<<dim3((DINPROJ + 127) / 128, NTOK / 128), 256, GEMM_SMEM>>>(
        x1h, x1l, wih, wil, nullptr, nullptr, Z, nullptr, nullptr, NTOK, DINPROJ, DMODEL);
    // 3. causal conv + silu
    conv_silu<<<dim3((CONVDIM + 255) / 256, NTOK), 256>>>(Z, conv_w, conv_b, xBC);
    // 4. SSM scan (+ D skip)
    ssm_scan<<<512, 128>>>(xBC, Z, dt_bias, A_log, Dvec, y);
    // 5. gated rmsnorm
    gated_rmsnorm<<<NTOK, 256>>>(y, Z, ssm_norm_w, y2h, y2l);
    // 6. out_proj + residual
    gemm_bf16<<<dim3(DMODEL / 128, NTOK / 128), 256, GEMM_SMEM>>>(
        y2h, y2l, woh, wol, hidden, nullptr, x2, nullptr, nullptr, NTOK, DMODEL, DINNER);
    // 7. post-norm
    rmsnorm1024<<<NTOK, 256>>>(x2, post_norm_w, h2h, h2l);
    // 8. MLP gate
    gemm_bf16<<<dim3((INTERD + 127) / 128, NTOK / 128), 256, GEMM_SMEM>>>(
        h2h, h2l, wgh, wgl, nullptr, nullptr, gg, nullptr, nullptr, NTOK, INTERD, DMODEL);
    // 9. MLP up + fused swiglu epilogue (split-bf16 out)
    gemm_bf16<<<dim3((INTERD + 127) / 128, NTOK / 128), 256, GEMM_SMEM>>>(
        h2h, h2l, wuh, wul, nullptr, gg, nullptr, ddh, ddl, NTOK, INTERD, DMODEL);
    // 10. down proj + residual -> out
    gemm_bf16<<<dim3(DMODEL / 128, NTOK / 128), 256, GEMM_SMEM>>>(
        ddh, ddl, wdh, wdl, x2, nullptr, out, nullptr, nullptr, NTOK, DMODEL, INTERD);
}

// round 7
// speedup vs baseline: 2.2233x; 1.0352x over previous
#include <cuda_runtime.h>
#include <cuda_bf16.h>
#include <cstdint>
#include <math.h>

// ---------------- problem constants ----------------
#define BATCH   2
#define SEQLEN  1024
#define DMODEL  1024
#define DSTATE  128
#define DCONV   4
#define HEADDIM 64
#define DINNER  2048
#define NHEADS  32
#define CONVDIM 2304     // DINNER + 2*DSTATE
#define DINPROJ 4384     // 2*DINNER + 2*DSTATE + NHEADS
#define INTERD  2752
#define NTOK    2048     // BATCH*SEQLEN
#define EPSV    1e-6f

// ---------------- fp32 scratch ----------------
__device__ float g_Z  [NTOK * DINPROJ];
__device__ float g_xBC[NTOK * CONVDIM];
__device__ float g_y  [NTOK * DINNER];
__device__ float g_x2 [NTOK * DMODEL];
__device__ float g_g  [NTOK * INTERD];

// ---------------- split-bf16 activations ----------------
__device__ __nv_bfloat16 g_x1h[NTOK * DMODEL], g_x1l[NTOK * DMODEL];
__device__ __nv_bfloat16 g_h2h[NTOK * DMODEL], g_h2l[NTOK * DMODEL];
__device__ __nv_bfloat16 g_y2h[NTOK * DINNER], g_y2l[NTOK * DINNER];
__device__ __nv_bfloat16 g_ddh[NTOK * INTERD], g_ddl[NTOK * INTERD];

// ---------------- split-bf16 weights ----------------
__device__ __nv_bfloat16 g_wih[DINPROJ * DMODEL], g_wil[DINPROJ * DMODEL];
__device__ __nv_bfloat16 g_woh[DMODEL * DINNER],  g_wol[DMODEL * DINNER];
__device__ __nv_bfloat16 g_wgh[INTERD * DMODEL],  g_wgl[INTERD * DMODEL];
__device__ __nv_bfloat16 g_wuh[INTERD * DMODEL],  g_wul[INTERD * DMODEL];
__device__ __nv_bfloat16 g_wdh[DMODEL * INTERD],  g_wdl[DMODEL * INTERD];

// ---------------- helpers ----------------
__device__ __forceinline__ uint32_t smem_u32(const void* p) {
    uint32_t a;
    asm("{ .reg .u64 t; cvta.to.shared.u64 t, %1; cvt.u32.u64 %0, t; }" : "=r"(a) : "l"(p));
    return a;
}
__device__ __forceinline__ float blockReduceSum(float v) {
    __shared__ float sb[32];
    int lane = threadIdx.x & 31;
    int w    = threadIdx.x >> 5;
    #pragma unroll
    for (int o = 16; o; o >>= 1) v += __shfl_xor_sync(0xffffffffu, v, o);
    if (lane == 0) sb[w] = v;
    __syncthreads();
    int nw = blockDim.x >> 5;
    float r = (threadIdx.x < (unsigned)nw) ? sb[threadIdx.x] : 0.f;
    if (w == 0) {
        #pragma unroll
        for (int o = 16; o; o >>= 1) r += __shfl_xor_sync(0xffffffffu, r, o);
        if (lane == 0) sb[0] = r;
    }
    __syncthreads();
    return sb[0];
}
__device__ __forceinline__ float siluf(float x) { return x * (1.0f / (1.0f + __expf(-x))); }

__device__ __forceinline__ void ldsm4(uint32_t* r, uint32_t addr) {
    asm volatile("ldmatrix.sync.aligned.m8n8.x4.shared.b16 {%0,%1,%2,%3}, [%4];"
                 : "=r"(r[0]), "=r"(r[1]), "=r"(r[2]), "=r"(r[3]) : "r"(addr));
}
__device__ __forceinline__ void mma16816(float* d, const uint32_t* a, const uint32_t* b) {
    asm volatile(
        "mma.sync.aligned.m16n8k16.row.col.f32.bf16.bf16.f32 "
        "{%0,%1,%2,%3}, {%4,%5,%6,%7}, {%8,%9}, {%0,%1,%2,%3};"
        : "+f"(d[0]), "+f"(d[1]), "+f"(d[2]), "+f"(d[3])
        : "r"(a[0]), "r"(a[1]), "r"(a[2]), "r"(a[3]), "r"(b[0]), "r"(b[1]));
}
__device__ __forceinline__ void split_bf16(float a, float b, uint32_t& hi, uint32_t& lo) {
    __nv_bfloat16 ha = __float2bfloat16(a), hb = __float2bfloat16(b);
    __nv_bfloat16 la = __float2bfloat16(a - __bfloat162float(ha));
    __nv_bfloat16 lb = __float2bfloat16(b - __bfloat162float(hb));
    __nv_bfloat162 th(ha, hb), tl(la, lb);
    hi = *reinterpret_cast<uint32_t*>(&th);
    lo = *reinterpret_cast<uint32_t*>(&tl);
}
__device__ __forceinline__ void cp_async16(uint32_t dst, const void* src, int src_bytes) {
    asm volatile("cp.async.cg.shared.global [%0], [%1], 16, %2;"
                 :: "r"(dst), "l"(src), "r"(src_bytes));
}
__device__ __forceinline__ void cp_commit() { asm volatile("cp.async.commit_group;" ::: "memory"); }
__device__ __forceinline__ void cp_wait0()  { asm volatile("cp.async.wait_group 0;" ::: "memory"); }

// ---------------- merged fp32 -> split-bf16 converter (3 segments) ----------------
__global__ void __launch_bounds__(256)
wsplit3(const float* __restrict__ a, __nv_bfloat16* __restrict__ ah, __nv_bfloat16* __restrict__ al, int na,
        const float* __restrict__ b, __nv_bfloat16* __restrict__ bh, __nv_bfloat16* __restrict__ bl, int nb,
        const float* __restrict__ c, __nv_bfloat16* __restrict__ ch, __nv_bfloat16* __restrict__ cl, int nc) {
    int i = blockIdx.x * 256 + threadIdx.x;
    const float* src; __nv_bfloat16 *oh, *ol; int j;
    if (i < na)                { src = a; oh = ah; ol = al; j = i; }
    else if (i < na + nb)      { src = b; oh = bh; ol = bl; j = i - na; }
    else if (i < na + nb + nc) { src = c; oh = ch; ol = cl; j = i - na - nb; }
    else return;
    float4 v = ((const float4*)src)[j];
    uint32_t h0, l0, h1, l1;
    split_bf16(v.x, v.y, h0, l0);
    split_bf16(v.z, v.w, h1, l1);
    ((uint2*)oh)[j] = make_uint2(h0, h1);
    ((uint2*)ol)[j] = make_uint2(l0, l1);
}

__global__ void __launch_bounds__(256) zero_f32(float* __restrict__ p, int n4) {
    int i = blockIdx.x * 256 + threadIdx.x;
    if (i < n4) ((float4*)p)[i] = make_float4(0.f, 0.f, 0.f, 0.f);
}

// ================= split-bf16 tensor-core GEMM: cp.async, single bar/chunk, opt split-K =================
#define KC 32
#define ROWB 40
#define STAGE_ELEMS (128 * ROWB)
#define STAGE_BYTES (4 * STAGE_ELEMS * 2)  // 40960 B
#define GEMM_SMEM (2 * STAGE_BYTES)        // 81920 B

extern __shared__ __align__(16) __nv_bfloat16 dsm[];

__global__ void __launch_bounds__(256, 2)
gemm_bf16(const __nv_bfloat16* __restrict__ Ah_, const __nv_bfloat16* __restrict__ Al_,
          const __nv_bfloat16* __restrict__ Wh_, const __nv_bfloat16* __restrict__ Wl_,
          const float* __restrict__ R, const float* __restrict__ G,
          float* __restrict__ Cf,
          __nv_bfloat16* __restrict__ Ch, __nv_bfloat16* __restrict__ Cl,
          int M, int N, int K, int kParts) {
    uint32_t sbase = smem_u32(dsm);
    int tid  = threadIdx.x;
    int wid  = tid >> 5;
    int lane = tid & 31;
    int wr   = wid & 3;
    int wc   = wid >> 2;
    int row0 = blockIdx.y * 128;
    int col0 = blockIdx.x * 128;
    int kbase = blockIdx.z * (K / kParts);
    int NC    = (K / kParts) / KC;

    float acc[2][8][4];
    #pragma unroll
    for (int mt = 0; mt < 2; mt++)
        #pragma unroll
        for (int nt = 0; nt < 8; nt++)
            #pragma unroll
            for (int q = 0; q < 4; q++) acc[mt][nt][q] = 0.f;

    int aRow  = wr * 32 + (lane & 15);
    int aColB = ((lane >> 4) & 1) * 16;
    int bRow  = wc * 64 + (lane & 7) + ((lane >> 4) & 1) * 8;
    int bColB = ((lane >> 3) & 1) * 16;

    int rowL[2], ceL[2];
    #pragma unroll
    for (int s = 0; s < 2; s++) {
        int idx = s * 256 + tid;
        rowL[s] = idx >> 2;
        ceL[s]  = (idx & 3) * 8;
    }
    int wrow0 = col0 + rowL[0], wrow1 = col0 + rowL[1];
    int sz0 = (wrow0 < N) ? 16 : 0, sz1 = (wrow1 < N) ? 16 : 0;
    int wsafe0 = (wrow0 < N) ? wrow0 : 0, wsafe1 = (wrow1 < N) ? wrow1 : 0;

    auto issue = [&](int c, int st) {
        uint32_t base = sbase + st * STAGE_BYTES;
        #pragma unroll
        for (int s = 0; s < 2; s++) {
            int row = rowL[s], ce = ceL[s];
            uint32_t doff = (uint32_t)(row * ROWB + ce) * 2;
            size_t goA = (size_t)(row0 + row) * K + kbase + c * KC + ce;
            cp_async16(base + doff,                   Ah_ + goA, 16);
            cp_async16(base + STAGE_ELEMS * 2 + doff, Al_ + goA, 16);
            size_t goW = (size_t)(s ? wsafe1 : wsafe0) * K + kbase + c * KC + ce;
            int sz = s ? sz1 : sz0;
            cp_async16(base + STAGE_ELEMS * 4 + doff, Wh_ + goW, sz);
            cp_async16(base + STAGE_ELEMS * 6 + doff, Wl_ + goW, sz);
        }
    };

    issue(0, 0);
    cp_commit();

    for (int c = 0; c < NC; c++) {
        cp_wait0();
        __syncthreads();          // copies of stage c visible; all reads of other stage done
        if (c + 1 < NC) { issue(c + 1, (c + 1) & 1); cp_commit(); }

        uint32_t base   = sbase + (c & 1) * STAGE_BYTES;
        uint32_t alBase = base + STAGE_ELEMS * 2;
        uint32_t bhBase = base + STAGE_ELEMS * 4;
        uint32_t blBase = base + STAGE_ELEMS * 6;

        #pragma unroll
        for (int ks = 0; ks < 2; ks++) {
            uint32_t Am[2][4], Al2[2][4];
            #pragma unroll
            for (int mt = 0; mt < 2; mt++) {
                uint32_t off = (uint32_t)((aRow + mt * 16) * (ROWB * 2) + ks * 32 + aColB);
                ldsm4(Am[mt],  base   + off);
                ldsm4(Al2[mt], alBase + off);
            }
            #pragma unroll
            for (int ntp = 0; ntp < 4; ntp++) {
                uint32_t Bm[4], Bl2[4];
                uint32_t off = (uint32_t)((bRow + ntp * 16) * (ROWB * 2) + ks * 32 + bColB);
                ldsm4(Bm,  bhBase + off);
                ldsm4(Bl2, blBase + off);
                #pragma unroll
                for (int mt = 0; mt < 2; mt++) {
                    mma16816(acc[mt][ntp * 2 + 0], Am[mt], &Bm[0]);
                    mma16816(acc[mt][ntp * 2 + 1], Am[mt], &Bm[2]);
                }
                #pragma unroll
                for (int mt = 0; mt < 2; mt++) {
                    mma16816(acc[mt][ntp * 2 + 0], Am[mt], &Bl2[0]);
                    mma16816(acc[mt][ntp * 2 + 1], Am[mt], &Bl2[2]);
                }
                #pragma unroll
                for (int mt = 0; mt < 2; mt++) {
                    mma16816(acc[mt][ntp * 2 + 0], Al2[mt], &Bm[0]);
                    mma16816(acc[mt][ntp * 2 + 1], Al2[mt], &Bm[2]);
                }
            }
        }
    }

    // ---- epilogue ----
    __syncthreads();
    int gid = lane >> 2;
    int tig = lane & 3;
    bool doAtomic = (kParts > 1);
    bool addR = (R != nullptr) && (blockIdx.z == 0);
    #pragma unroll
    for (int mt = 0; mt < 2; mt++) {
        int r0 = row0 + wr * 32 + mt * 16 + gid;
        #pragma unroll
        for (int nt = 0; nt < 8; nt++) {
            int col = col0 + wc * 64 + nt * 8 + tig * 2;
            if (col < N) {
                float2 v0 = make_float2(acc[mt][nt][0], acc[mt][nt][1]);
                float2 v1 = make_float2(acc[mt][nt][2], acc[mt][nt][3]);
                if (G) {
                    float2 g0 = *(const float2*)(G + (size_t)r0 * N + col);
                    float2 g1 = *(const float2*)(G + (size_t)(r0 + 8) * N + col);
                    v0.x = siluf(g0.x) * v0.x; v0.y = siluf(g0.y) * v0.y;
                    v1.x = siluf(g1.x) * v1.x; v1.y = siluf(g1.y) * v1.y;
                }
                if (addR) {
                    float2 r0v = *(const float2*)(R + (size_t)r0 * N + col);
                    float2 r1v = *(const float2*)(R + (size_t)(r0 + 8) * N + col);
                    v0.x += r0v.x; v0.y += r0v.y;
                    v1.x += r1v.x; v1.y += r1v.y;
                }
                if (doAtomic) {
                    atomicAdd(Cf + (size_t)r0 * N + col,       v0.x);
                    atomicAdd(Cf + (size_t)r0 * N + col + 1,   v0.y);
                    atomicAdd(Cf + (size_t)(r0 + 8) * N + col,     v1.x);
                    atomicAdd(Cf + (size_t)(r0 + 8) * N + col + 1, v1.y);
                } else if (Cf) {
                    *(float2*)(Cf + (size_t)r0 * N + col)       = v0;
                    *(float2*)(Cf + (size_t)(r0 + 8) * N + col) = v1;
                } else {
                    uint32_t h0, l0;
                    split_bf16(v0.x, v0.y, h0, l0);
                    *(uint32_t*)(Ch + (size_t)r0 * N + col) = h0;
                    *(uint32_t*)(Cl + (size_t)r0 * N + col) = l0;
                    split_bf16(v1.x, v1.y, h0, l0);
                    *(uint32_t*)(Ch + (size_t)(r0 + 8) * N + col) = h0;
                    *(uint32_t*)(Cl + (size_t)(r0 + 8) * N + col) = l0;
                }
            }
        }
    }
}

// ---------------- rmsnorm over D=1024, writes split-bf16 ----------------
__global__ void __launch_bounds__(256) rmsnorm1024(const float* __restrict__ x,
                                                   const float* __restrict__ w,
                                                   __nv_bfloat16* __restrict__ oh,
                                                   __nv_bfloat16* __restrict__ ol) {
    int tok = blockIdx.x;
    int tid = threadIdx.x;
    const float4* xp = (const float4*)(x + (size_t)tok * DMODEL);
    float4 v = xp[tid];
    float ss = v.x * v.x + v.y * v.y + v.z * v.z + v.w * v.w;
    ss = blockReduceSum(ss);
    float rs = rsqrtf(ss * (1.0f / DMODEL) + EPSV);
    float4 wv = ((const float4*)w)[tid];
    float4 o;
    o.x = v.x * rs * wv.x; o.y = v.y * rs * wv.y;
    o.z = v.z * rs * wv.z; o.w = v.w * rs * wv.w;
    uint32_t h0, l0, h1, l1;
    split_bf16(o.x, o.y, h0, l0);
    split_bf16(o.z, o.w, h1, l1);
    ((uint2*)(oh + (size_t)tok * DMODEL))[tid] = make_uint2(h0, h1);
    ((uint2*)(ol + (size_t)tok * DMODEL))[tid] = make_uint2(l0, l1);
}

// ---------------- gated rmsnorm over D_INNER=2048, writes split-bf16 ----------------
__global__ void __launch_bounds__(256) gated_rmsnorm(const float* __restrict__ y,
                                                     const float* __restrict__ Z,
                                                     const float* __restrict__ w,
                                                     __nv_bfloat16* __restrict__ oh,
                                                     __nv_bfloat16* __restrict__ ol) {
    int tok = blockIdx.x;
    int tid = threadIdx.x;
    const float4* yp = (const float4*)(y + (size_t)tok * DINNER);
    const float4* zp = (const float4*)(Z + (size_t)tok * DINPROJ);
    float4 v[2];
    float ss = 0.f;
    #pragma unroll
    for (int q = 0; q < 2; q++) {
        float4 yv = yp[tid + q * 256];
        float4 zv = zp[tid + q * 256];
        float4 t;
        t.x = yv.x * siluf(zv.x); t.y = yv.y * siluf(zv.y);
        t.z = yv.z * siluf(zv.z); t.w = yv.w * siluf(zv.w);
        v[q] = t;
        ss += t.x * t.x + t.y * t.y + t.z * t.z + t.w * t.w;
    }
    ss = blockReduceSum(ss);
    float rs = rsqrtf(ss * (1.0f / DINNER) + EPSV);
    #pragma unroll
    for (int q = 0; q < 2; q++) {
        float4 wv = ((const float4*)w)[tid + q * 256];
        float4 o;
        o.x = v[q].x * rs * wv.x; o.y = v[q].y * rs * wv.y;
        o.z = v[q].z * rs * wv.z; o.w = v[q].w * rs * wv.w;
        uint32_t h0, l0, h1, l1;
        split_bf16(o.x, o.y, h0, l0);
        split_bf16(o.z, o.w, h1, l1);
        ((uint2*)(oh + (size_t)tok * DINNER))[tid + q * 256] = make_uint2(h0, h1);
        ((uint2*)(ol + (size_t)tok * DINNER))[tid + q * 256] = make_uint2(l0, l1);
    }
}

// ---------------- causal depthwise conv (width 4) + silu ----------------
__global__ void __launch_bounds__(256) conv_silu(const float* __restrict__ Z,
                                                 const float* __restrict__ cw,
                                                 const float* __restrict__ cb,
                                                 float* __restrict__ out) {
    int c   = blockIdx.x * 256 + threadIdx.x;
    int tok = blockIdx.y;
    if (c >= CONVDIM) return;
    int l = tok & (SEQLEN - 1);
    float w0 = cw[c * 4 + 0], w1 = cw[c * 4 + 1], w2 = cw[c * 4 + 2], w3 = cw[c * 4 + 3];
    const float* zc = Z + (size_t)tok * DINPROJ + DINNER + c;
    float acc = cb[c];
    acc += zc[0] * w3;
    if (l >= 1) acc += zc[-(ptrdiff_t)DINPROJ]     * w2;
    if (l >= 2) acc += zc[-(ptrdiff_t)DINPROJ * 2] * w1;
    if (l >= 3) acc += zc[-(ptrdiff_t)DINPROJ * 3] * w0;
    out[(size_t)tok * CONVDIM + c] = siluf(acc);
}

// ---------------- sequential SSM scan: 8-way p-split, 512 blocks ----------------
__global__ void __launch_bounds__(128) ssm_scan(const float* __restrict__ xBC,
                                                const float* __restrict__ Z,
                                                const float* __restrict__ dt_bias,
                                                const float* __restrict__ A_log,
                                                const float* __restrict__ Dp,
                                                float* __restrict__ y) {
    int bid   = blockIdx.x;          // 512 = b(2) * h(32) * oct(8)
    int b     = bid >> 8;
    int h     = (bid >> 3) & 31;
    int oct   = bid & 7;
    int pbase = oct * 8;
    int t     = threadIdx.x;

    __shared__ float s_dtx[2][2][8];
    __shared__ float s_x[2][2][8];
    __shared__ float s_red[2][8][144];

    float hs[8];
    #pragma unroll
    for (int p = 0; p < 8; p++) hs[p] = 0.f;

    float Ahv = -__expf(A_log[h]);
    float dbh = dt_bias[h];
    float Dh  = Dp[h];
    int   rp  = t >> 4;
    int   ri  = t & 15;

    const float* xrow  = xBC + (size_t)b * SEQLEN * CONVDIM;
    const float* dtrow = Z + (size_t)b * SEQLEN * DINPROJ + (DINPROJ - NHEADS) + h;
    float*       yrow  = y + (size_t)b * SEQLEN * DINNER + h * HEADDIM + pbase;

    float Bv[2], Cv[2], dAc[2];
    float B1[2], C1[2], dt1[2], x1v[2];

    #pragma unroll
    for (int q = 0; q < 2; q++) {
        const float* xr = xrow + (size_t)q * CONVDIM;
        Bv[q] = xr[DINNER + t];
        Cv[q] = xr[DINNER + DSTATE + t];
        float dts = dtrow[(size_t)q * DINPROJ] + dbh;
        float dtv = (dts > 20.f) ? dts : __logf(1.f + __expf(dts));
        dAc[q] = __expf(dtv * Ahv);
        if (t < 8) {
            float x0 = xr[h * HEADDIM + pbase + t];
            s_dtx[0][q][t] = dtv * x0; s_x[0][q][t] = x0;
        }
    }
    #pragma unroll
    for (int q = 0; q < 2; q++) {
        const float* xr = xrow + (size_t)(2 + q) * CONVDIM;
        B1[q]  = xr[DINNER + t];
        C1[q]  = xr[DINNER + DSTATE + t];
        dt1[q] = dtrow[(size_t)(2 + q) * DINPROJ];
        x1v[q] = (t < 8) ? xr[h * HEADDIM + pbase + t] : 0.f;
    }
    __syncthreads();

    int cur = 0;
    for (int i = 0; i < SEQLEN / 2; i++) {
        int nxt = cur ^ 1;
        float dAn[2] = {0.f, 0.f};
        if (i < SEQLEN / 2 - 1) {
            #pragma unroll
            for (int q = 0; q < 2; q++) {
                float dts = dt1[q] + dbh;
                float dtv = (dts > 20.f) ? dts : __logf(1.f + __expf(dts));
                dAn[q] = __expf(dtv * Ahv);
                if (t < 8) { s_dtx[nxt][q][t] = dtv * x1v[q]; s_x[nxt][q][t] = x1v[q]; }
            }
        }
        #pragma unroll
        for (int q = 0; q < 2; q++) {
            float dAq = dAc[q], Bq = Bv[q], Cq = Cv[q];
            #pragma unroll
            for (int p = 0; p < 8; p++) {
                hs[p] = fmaf(hs[p], dAq, s_dtx[cur][q][p] * Bq);
                s_red[q][p][t] = hs[p] * Cq;
            }
        }
        __syncthreads();

        #pragma unroll
        for (int q = 0; q < 2; q++) {
            float sum = 0.f;
            #pragma unroll
            for (int k = 0; k < 8; k++) sum += s_red[q][rp][k * 16 + ri];
            #pragma unroll
            for (int o = 8; o; o >>= 1) sum += __shfl_xor_sync(0xffffffffu, sum, o, 16);
            if (ri == 0)
                yrow[(size_t)(2 * i + q) * DINNER + rp] = sum + Dh * s_x[cur][q][rp];
        }

        dAc[0] = dAn[0]; dAc[1] = dAn[1];
        Bv[0] = B1[0]; Bv[1] = B1[1];
        Cv[0] = C1[0]; Cv[1] = C1[1];
        if (i < SEQLEN / 2 - 2) {
            #pragma unroll
            for (int q = 0; q < 2; q++) {
                int s = 2 * i + 4 + q;
                const float* xr = xrow + (size_t)s * CONVDIM;
                B1[q]  = xr[DINNER + t];
                C1[q]  = xr[DINNER + DSTATE + t];
                dt1[q] = dtrow[(size_t)s * DINPROJ];
                x1v[q] = (t < 8) ? xr[h * HEADDIM + pbase + t] : 0.f;
            }
        }
        __syncthreads();
        cur = nxt;
    }
}

// ---------------- launch ----------------
extern "C" void kernel_launch(void* const* d_in, const int* in_sizes, int n_in,
                              void* d_out, int out_size) {
    const float* hidden     = (const float*)d_in[0];
    const float* norm_w     = (const float*)d_in[1];
    const float* in_proj_w  = (const float*)d_in[2];
    const float* conv_w     = (const float*)d_in[3];
    const float* conv_b     = (const float*)d_in[4];
    const float* dt_bias    = (const float*)d_in[5];
    const float* A_log      = (const float*)d_in[6];
    const float* Dvec       = (const float*)d_in[7];
    const float* ssm_norm_w = (const float*)d_in[8];
    const float* out_proj_w = (const float*)d_in[9];
    const float* post_norm_w= (const float*)d_in[10];
    const float* gate_w     = (const float*)d_in[11];
    const float* up_w       = (const float*)d_in[12];
    const float* down_w     = (const float*)d_in[13];
    float* out = (float*)d_out;

    float *Z, *xBC, *y, *x2, *gg;
    cudaGetSymbolAddress((void**)&Z,   g_Z);
    cudaGetSymbolAddress((void**)&xBC, g_xBC);
    cudaGetSymbolAddress((void**)&y,   g_y);
    cudaGetSymbolAddress((void**)&x2,  g_x2);
    cudaGetSymbolAddress((void**)&gg,  g_g);

    __nv_bfloat16 *x1h, *x1l, *h2h, *h2l, *y2h, *y2l, *ddh, *ddl;
    cudaGetSymbolAddress((void**)&x1h, g_x1h); cudaGetSymbolAddress((void**)&x1l, g_x1l);
    cudaGetSymbolAddress((void**)&h2h, g_h2h); cudaGetSymbolAddress((void**)&h2l, g_h2l);
    cudaGetSymbolAddress((void**)&y2h, g_y2h); cudaGetSymbolAddress((void**)&y2l, g_y2l);
    cudaGetSymbolAddress((void**)&ddh, g_ddh); cudaGetSymbolAddress((void**)&ddl, g_ddl);

    __nv_bfloat16 *wih, *wil, *woh, *wol, *wgh, *wgl, *wuh, *wul, *wdh, *wdl;
    cudaGetSymbolAddress((void**)&wih, g_wih); cudaGetSymbolAddress((void**)&wil, g_wil);
    cudaGetSymbolAddress((void**)&woh, g_woh); cudaGetSymbolAddress((void**)&wol, g_wol);
    cudaGetSymbolAddress((void**)&wgh, g_wgh); cudaGetSymbolAddress((void**)&wgl, g_wgl);
    cudaGetSymbolAddress((void**)&wuh, g_wuh); cudaGetSymbolAddress((void**)&wul, g_wul);
    cudaGetSymbolAddress((void**)&wdh, g_wdh); cudaGetSymbolAddress((void**)&wdl, g_wdl);

    cudaFuncSetAttribute(gemm_bf16, cudaFuncAttributeMaxDynamicSharedMemorySize, GEMM_SMEM);

    const int nIn = DINPROJ * DMODEL / 4, nOut = DMODEL * DINNER / 4;
    const int nGU = INTERD * DMODEL / 4,  nDn  = DMODEL * INTERD / 4;

    // 0,1: weight pre-conversion (2 merged launches)
    wsplit3<<<(nIn + nOut + nGU + 255) / 256, 256>>>(
        in_proj_w, wih, wil, nIn, out_proj_w, woh, wol, nOut, gate_w, wgh, wgl, nGU);
    wsplit3<<<(nGU + nDn + 255) / 256, 256>>>(
        up_w, wuh, wul, nGU, down_w, wdh, wdl, nDn, nullptr, nullptr, nullptr, 0);

    // 2: pre-norm
    rmsnorm1024<<<NTOK, 256>>>(hidden, norm_w, x1h, x1l);
    // 3: in_proj
    gemm_bf16<<<dim3((DINPROJ + 127) / 128, NTOK / 128, 1), 256, GEMM_SMEM>>>(
        x1h, x1l, wih, wil, nullptr, nullptr, Z, nullptr, nullptr, NTOK, DINPROJ, DMODEL, 1);
    // 4: causal conv + silu
    conv_silu<<<dim3((CONVDIM + 255) / 256, NTOK), 256>>>(Z, conv_w, conv_b, xBC);
    // 5: SSM scan  (ncu -s 5 captures this)
    ssm_scan<<<512, 128>>>(xBC, Z, dt_bias, A_log, Dvec, y);
    // 6: gated rmsnorm
    gated_rmsnorm<<<NTOK, 256>>>(y, Z, ssm_norm_w, y2h, y2l);
    // 7: zero x2; 8: out_proj split-K2 + residual (atomic)
    zero_f32<<<(NTOK * DMODEL / 4 + 255) / 256, 256>>>(x2, NTOK * DMODEL / 4);
    gemm_bf16<<<dim3(DMODEL / 128, NTOK / 128, 2), 256, GEMM_SMEM>>>(
        y2h, y2l, woh, wol, hidden, nullptr, x2, nullptr, nullptr, NTOK, DMODEL, DINNER, 2);
    // 9: post-norm
    rmsnorm1024<<<NTOK, 256>>>(x2, post_norm_w, h2h, h2l);
    // 10: MLP gate
    gemm_bf16<<<dim3((INTERD + 127) / 128, NTOK / 128, 1), 256, GEMM_SMEM>>>(
        h2h, h2l, wgh, wgl, nullptr, nullptr, gg, nullptr, nullptr, NTOK, INTERD, DMODEL, 1);
    // 11: MLP up + fused swiglu epilogue
    gemm_bf16<<<dim3((INTERD + 127) / 128, NTOK / 128, 1), 256, GEMM_SMEM>>>(
        h2h, h2l, wuh, wul, nullptr, gg, nullptr, ddh, ddl, NTOK, INTERD, DMODEL, 1);
    // 12: zero out; 13: down proj split-K2 + residual (atomic)
    zero_f32<<<(NTOK * DMODEL / 4 + 255) / 256, 256>>>(out, NTOK * DMODEL / 4);
    gemm_bf16<<<dim3(DMODEL / 128, NTOK / 128, 2), 256, GEMM_SMEM>>>(
        ddh, ddl, wdh, wdl, x2, nullptr, out, nullptr, nullptr, NTOK, DMODEL, INTERD, 2);
}

// round 12
// speedup vs baseline: 2.3297x; 1.0478x over previous
#include <cuda_runtime.h>
#include <cuda_bf16.h>
#include <cstdint>
#include <math.h>

// ---------------- problem constants ----------------
#define BATCH   2
#define SEQLEN  1024
#define DMODEL  1024
#define DSTATE  128
#define DCONV   4
#define HEADDIM 64
#define DINNER  2048
#define NHEADS  32
#define CONVDIM 2304     // DINNER + 2*DSTATE
#define DINPROJ 4384     // 2*DINNER + 2*DSTATE + NHEADS
#define INTERD  2752
#define NTOK    2048     // BATCH*SEQLEN
#define EPSV    1e-6f

// ---------------- fp32 scratch ----------------
__device__ float g_Z  [NTOK * DINPROJ];   // in_proj out; later reused for out_proj split-K partials
__device__ float g_xBC[NTOK * CONVDIM];
__device__ float g_y  [NTOK * DINNER];
__device__ float g_x2 [NTOK * DMODEL];
__device__ float g_g  [NTOK * INTERD];    // gate out; later reused for down split-K partials
__device__ float g_u  [NTOK * INTERD];    // up out

// ---------------- split-bf16 activations ----------------
__device__ __nv_bfloat16 g_x1h[NTOK * DMODEL], g_x1l[NTOK * DMODEL];
__device__ __nv_bfloat16 g_h2h[NTOK * DMODEL], g_h2l[NTOK * DMODEL];
__device__ __nv_bfloat16 g_y2h[NTOK * DINNER], g_y2l[NTOK * DINNER];
__device__ __nv_bfloat16 g_ddh[NTOK * INTERD], g_ddl[NTOK * INTERD];

// ---------------- split-bf16 weights ----------------
__device__ __nv_bfloat16 g_wih[DINPROJ * DMODEL], g_wil[DINPROJ * DMODEL];
__device__ __nv_bfloat16 g_woh[DMODEL * DINNER],  g_wol[DMODEL * DINNER];
__device__ __nv_bfloat16 g_wgh[INTERD * DMODEL],  g_wgl[INTERD * DMODEL];
__device__ __nv_bfloat16 g_wuh[INTERD * DMODEL],  g_wul[INTERD * DMODEL];
__device__ __nv_bfloat16 g_wdh[DMODEL * INTERD],  g_wdl[DMODEL * INTERD];

// ---------------- helpers ----------------
__device__ __forceinline__ uint32_t smem_u32(const void* p) {
    uint32_t a;
    asm("{ .reg .u64 t; cvta.to.shared.u64 t, %1; cvt.u32.u64 %0, t; }" : "=r"(a) : "l"(p));
    return a;
}
__device__ __forceinline__ float blockReduceSum(float v) {
    __shared__ float sb[32];
    int lane = threadIdx.x & 31;
    int w    = threadIdx.x >> 5;
    #pragma unroll
    for (int o = 16; o; o >>= 1) v += __shfl_xor_sync(0xffffffffu, v, o);
    if (lane == 0) sb[w] = v;
    __syncthreads();
    int nw = blockDim.x >> 5;
    float r = (threadIdx.x < (unsigned)nw) ? sb[threadIdx.x] : 0.f;
    if (w == 0) {
        #pragma unroll
        for (int o = 16; o; o >>= 1) r += __shfl_xor_sync(0xffffffffu, r, o);
        if (lane == 0) sb[0] = r;
    }
    __syncthreads();
    return sb[0];
}
__device__ __forceinline__ float siluf(float x) { return x * (1.0f / (1.0f + __expf(-x))); }

__device__ __forceinline__ void ldsm4(uint32_t* r, uint32_t addr) {
    asm volatile("ldmatrix.sync.aligned.m8n8.x4.shared.b16 {%0,%1,%2,%3}, [%4];"
                 : "=r"(r[0]), "=r"(r[1]), "=r"(r[2]), "=r"(r[3]) : "r"(addr));
}
__device__ __forceinline__ void mma16816(float* d, const uint32_t* a, const uint32_t* b) {
    asm volatile(
        "mma.sync.aligned.m16n8k16.row.col.f32.bf16.bf16.f32 "
        "{%0,%1,%2,%3}, {%4,%5,%6,%7}, {%8,%9}, {%0,%1,%2,%3};"
        : "+f"(d[0]), "+f"(d[1]), "+f"(d[2]), "+f"(d[3])
        : "r"(a[0]), "r"(a[1]), "r"(a[2]), "r"(a[3]), "r"(b[0]), "r"(b[1]));
}
__device__ __forceinline__ void split_bf16(float a, float b, uint32_t& hi, uint32_t& lo) {
    __nv_bfloat16 ha = __float2bfloat16(a), hb = __float2bfloat16(b);
    __nv_bfloat16 la = __float2bfloat16(a - __bfloat162float(ha));
    __nv_bfloat16 lb = __float2bfloat16(b - __bfloat162float(hb));
    __nv_bfloat162 th(ha, hb), tl(la, lb);
    hi = *reinterpret_cast<uint32_t*>(&th);
    lo = *reinterpret_cast<uint32_t*>(&tl);
}
__device__ __forceinline__ void cp_async16(uint32_t dst, const void* src, int src_bytes) {
    asm volatile("cp.async.cg.shared.global [%0], [%1], 16, %2;"
                 :: "r"(dst), "l"(src), "r"(src_bytes));
}
__device__ __forceinline__ void cp_commit() { asm volatile("cp.async.commit_group;" ::: "memory"); }
__device__ __forceinline__ void cp_wait0()  { asm volatile("cp.async.wait_group 0;" ::: "memory"); }

// ---------------- merged fp32 -> split-bf16 converter (3 segments) ----------------
__global__ void __launch_bounds__(256)
wsplit3(const float* __restrict__ a, __nv_bfloat16* __restrict__ ah, __nv_bfloat16* __restrict__ al, int na,
        const float* __restrict__ b, __nv_bfloat16* __restrict__ bh, __nv_bfloat16* __restrict__ bl, int nb,
        const float* __restrict__ c, __nv_bfloat16* __restrict__ ch, __nv_bfloat16* __restrict__ cl, int nc) {
    int i = blockIdx.x * 256 + threadIdx.x;
    const float* src; __nv_bfloat16 *oh, *ol; int j;
    if (i < na)                { src = a; oh = ah; ol = al; j = i; }
    else if (i < na + nb)      { src = b; oh = bh; ol = bl; j = i - na; }
    else if (i < na + nb + nc) { src = c; oh = ch; ol = cl; j = i - na - nb; }
    else return;
    float4 v = ((const float4*)src)[j];
    uint32_t h0, l0, h1, l1;
    split_bf16(v.x, v.y, h0, l0);
    split_bf16(v.z, v.w, h1, l1);
    ((uint2*)oh)[j] = make_uint2(h0, h1);
    ((uint2*)ol)[j] = make_uint2(l0, l1);
}

// ================= split-bf16 tensor-core GEMM =================
// Modes: dual-weight (Wh2 != null): blockIdx.z selects {Wh,Cf} vs {Wh2,Cf2}
//        split-K (kParts>1): blockIdx.z = K-part, output partial at Cf + z*M*N
#define KC 32
#define ROWB 40
#define STAGE_ELEMS (128 * ROWB)
#define STAGE_BYTES (4 * STAGE_ELEMS * 2)  // 40960 B
#define GEMM_SMEM (2 * STAGE_BYTES)        // 81920 B

extern __shared__ __align__(16) __nv_bfloat16 dsm[];

__global__ void __launch_bounds__(256, 2)
gemm_bf16(const __nv_bfloat16* __restrict__ Ah_, const __nv_bfloat16* __restrict__ Al_,
          const __nv_bfloat16* __restrict__ Wh_, const __nv_bfloat16* __restrict__ Wl_,
          const __nv_bfloat16* __restrict__ Wh2_, const __nv_bfloat16* __restrict__ Wl2_,
          float* __restrict__ Cf, float* __restrict__ Cf2,
          int M, int N, int K, int kParts) {
    uint32_t sbase = smem_u32(dsm);
    int tid  = threadIdx.x;
    int wid  = tid >> 5;
    int lane = tid & 31;
    int wr   = wid & 3;
    int wc   = wid >> 2;
    int row0 = blockIdx.y * 128;
    int col0 = blockIdx.x * 128;

    int kbase = 0;
    float* outp = Cf;
    if (kParts > 1) {
        kbase = blockIdx.z * (K / kParts);
        outp  = Cf + (size_t)blockIdx.z * M * N;
    } else if (Wh2_ && blockIdx.z == 1) {
        Wh_ = Wh2_; Wl_ = Wl2_; outp = Cf2;
    }
    int NC = (K / kParts) / KC;

    float acc[2][8][4];
    #pragma unroll
    for (int mt = 0; mt < 2; mt++)
        #pragma unroll
        for (int nt = 0; nt < 8; nt++)
            #pragma unroll
            for (int q = 0; q < 4; q++) acc[mt][nt][q] = 0.f;

    int aRow  = wr * 32 + (lane & 15);
    int aColB = ((lane >> 4) & 1) * 16;
    int bRow  = wc * 64 + (lane & 7) + ((lane >> 4) & 1) * 8;
    int bColB = ((lane >> 3) & 1) * 16;

    int rowL[2], ceL[2];
    #pragma unroll
    for (int s = 0; s < 2; s++) {
        int idx = s * 256 + tid;
        rowL[s] = idx >> 2;
        ceL[s]  = (idx & 3) * 8;
    }
    int wrow0 = col0 + rowL[0], wrow1 = col0 + rowL[1];
    int sz0 = (wrow0 < N) ? 16 : 0, sz1 = (wrow1 < N) ? 16 : 0;
    int wsafe0 = (wrow0 < N) ? wrow0 : 0, wsafe1 = (wrow1 < N) ? wrow1 : 0;

    auto issue = [&](int c, int st) {
        uint32_t base = sbase + st * STAGE_BYTES;
        #pragma unroll
        for (int s = 0; s < 2; s++) {
            int row = rowL[s], ce = ceL[s];
            uint32_t doff = (uint32_t)(row * ROWB + ce) * 2;
            size_t goA = (size_t)(row0 + row) * K + kbase + c * KC + ce;
            cp_async16(base + doff,                   Ah_ + goA, 16);
            cp_async16(base + STAGE_ELEMS * 2 + doff, Al_ + goA, 16);
            size_t goW = (size_t)(s ? wsafe1 : wsafe0) * K + kbase + c * KC + ce;
            int sz = s ? sz1 : sz0;
            cp_async16(base + STAGE_ELEMS * 4 + doff, Wh_ + goW, sz);
            cp_async16(base + STAGE_ELEMS * 6 + doff, Wl_ + goW, sz);
        }
    };

    issue(0, 0);
    cp_commit();

    for (int c = 0; c < NC; c++) {
        cp_wait0();
        __syncthreads();
        if (c + 1 < NC) { issue(c + 1, (c + 1) & 1); cp_commit(); }

        uint32_t base   = sbase + (c & 1) * STAGE_BYTES;
        uint32_t alBase = base + STAGE_ELEMS * 2;
        uint32_t bhBase = base + STAGE_ELEMS * 4;
        uint32_t blBase = base + STAGE_ELEMS * 6;

        #pragma unroll
        for (int ks = 0; ks < 2; ks++) {
            uint32_t Am[2][4], Al2[2][4];
            #pragma unroll
            for (int mt = 0; mt < 2; mt++) {
                uint32_t off = (uint32_t)((aRow + mt * 16) * (ROWB * 2) + ks * 32 + aColB);
                ldsm4(Am[mt],  base   + off);
                ldsm4(Al2[mt], alBase + off);
            }
            // software-pipelined B fragments: load ntp+1 while mma'ing ntp
            uint32_t Bb[2][2][4];
            {
                uint32_t off0 = (uint32_t)(bRow * (ROWB * 2) + ks * 32 + bColB);
                ldsm4(Bb[0][0], bhBase + off0);
                ldsm4(Bb[0][1], blBase + off0);
            }
            #pragma unroll
            for (int ntp = 0; ntp < 4; ntp++) {
                int cb = ntp & 1, nb = cb ^ 1;
                if (ntp < 3) {
                    uint32_t off = (uint32_t)((bRow + (ntp + 1) * 16) * (ROWB * 2) + ks * 32 + bColB);
                    ldsm4(Bb[nb][0], bhBase + off);
                    ldsm4(Bb[nb][1], blBase + off);
                }
                #pragma unroll
                for (int mt = 0; mt < 2; mt++) {
                    mma16816(acc[mt][ntp * 2 + 0], Am[mt], &Bb[cb][0][0]);
                    mma16816(acc[mt][ntp * 2 + 1], Am[mt], &Bb[cb][0][2]);
                }
                #pragma unroll
                for (int mt = 0; mt < 2; mt++) {
                    mma16816(acc[mt][ntp * 2 + 0], Am[mt], &Bb[cb][1][0]);
                    mma16816(acc[mt][ntp * 2 + 1], Am[mt], &Bb[cb][1][2]);
                }
                #pragma unroll
                for (int mt = 0; mt < 2; mt++) {
                    mma16816(acc[mt][ntp * 2 + 0], Al2[mt], &Bb[cb][0][0]);
                    mma16816(acc[mt][ntp * 2 + 1], Al2[mt], &Bb[cb][0][2]);
                }
            }
        }
    }

    // ---- epilogue: plain fp32 stores ----
    __syncthreads();
    int gid = lane >> 2;
    int tig = lane & 3;
    #pragma unroll
    for (int mt = 0; mt < 2; mt++) {
        int r0 = row0 + wr * 32 + mt * 16 + gid;
        #pragma unroll
        for (int nt = 0; nt < 8; nt++) {
            int col = col0 + wc * 64 + nt * 8 + tig * 2;
            if (col < N) {
                *(float2*)(outp + (size_t)r0 * N + col) =
                    make_float2(acc[mt][nt][0], acc[mt][nt][1]);
                *(float2*)(outp + (size_t)(r0 + 8) * N + col) =
                    make_float2(acc[mt][nt][2], acc[mt][nt][3]);
            }
        }
    }
}

// ---------------- rmsnorm over D=1024, writes split-bf16 ----------------
__global__ void __launch_bounds__(256) rmsnorm1024(const float* __restrict__ x,
                                                   const float* __restrict__ w,
                                                   __nv_bfloat16* __restrict__ oh,
                                                   __nv_bfloat16* __restrict__ ol) {
    int tok = blockIdx.x;
    int tid = threadIdx.x;
    const float4* xp = (const float4*)(x + (size_t)tok * DMODEL);
    float4 v = xp[tid];
    float ss = v.x * v.x + v.y * v.y + v.z * v.z + v.w * v.w;
    ss = blockReduceSum(ss);
    float rs = rsqrtf(ss * (1.0f / DMODEL) + EPSV);
    float4 wv = ((const float4*)w)[tid];
    float4 o;
    o.x = v.x * rs * wv.x; o.y = v.y * rs * wv.y;
    o.z = v.z * rs * wv.z; o.w = v.w * rs * wv.w;
    uint32_t h0, l0, h1, l1;
    split_bf16(o.x, o.y, h0, l0);
    split_bf16(o.z, o.w, h1, l1);
    ((uint2*)(oh + (size_t)tok * DMODEL))[tid] = make_uint2(h0, h1);
    ((uint2*)(ol + (size_t)tok * DMODEL))[tid] = make_uint2(l0, l1);
}

// ---------------- rmsnorm of (hidden + p0 + p1): writes x2 (fp32) + split-bf16 ----------------
__global__ void __launch_bounds__(256) rmsnorm_sum3(const float* __restrict__ hid,
                                                    const float* __restrict__ p0,
                                                    const float* __restrict__ p1,
                                                    const float* __restrict__ w,
                                                    float* __restrict__ x2out,
                                                    __nv_bfloat16* __restrict__ oh,
                                                    __nv_bfloat16* __restrict__ ol) {
    int tok = blockIdx.x;
    int tid = threadIdx.x;
    size_t off = (size_t)tok * DMODEL;
    float4 a = ((const float4*)(hid + off))[tid];
    float4 b = ((const float4*)(p0  + off))[tid];
    float4 c = ((const float4*)(p1  + off))[tid];
    float4 v;
    v.x = a.x + b.x + c.x; v.y = a.y + b.y + c.y;
    v.z = a.z + b.z + c.z; v.w = a.w + b.w + c.w;
    ((float4*)(x2out + off))[tid] = v;
    float ss = v.x * v.x + v.y * v.y + v.z * v.z + v.w * v.w;
    ss = blockReduceSum(ss);
    float rs = rsqrtf(ss * (1.0f / DMODEL) + EPSV);
    float4 wv = ((const float4*)w)[tid];
    float4 o;
    o.x = v.x * rs * wv.x; o.y = v.y * rs * wv.y;
    o.z = v.z * rs * wv.z; o.w = v.w * rs * wv.w;
    uint32_t h0, l0, h1, l1;
    split_bf16(o.x, o.y, h0, l0);
    split_bf16(o.z, o.w, h1, l1);
    ((uint2*)(oh + off))[tid] = make_uint2(h0, h1);
    ((uint2*)(ol + off))[tid] = make_uint2(l0, l1);
}

// ---------------- final residual: out = x2 + p0 + p1 ----------------
__global__ void __launch_bounds__(256) add3(const float* __restrict__ x2,
                                            const float* __restrict__ p0,
                                            const float* __restrict__ p1,
                                            float* __restrict__ out, int n4) {
    int i = blockIdx.x * 256 + threadIdx.x;
    if (i < n4) {
        float4 a = ((const float4*)x2)[i];
        float4 b = ((const float4*)p0)[i];
        float4 c = ((const float4*)p1)[i];
        float4 v;
        v.x = a.x + b.x + c.x; v.y = a.y + b.y + c.y;
        v.z = a.z + b.z + c.z; v.w = a.w + b.w + c.w;
        ((float4*)out)[i] = v;
    }
}

// ---------------- swiglu + split: dd = split_bf16(silu(g) * u) ----------------
__global__ void __launch_bounds__(256) swiglu_split(const float* __restrict__ g,
                                                    const float* __restrict__ u,
                                                    __nv_bfloat16* __restrict__ oh,
                                                    __nv_bfloat16* __restrict__ ol, int n4) {
    int i = blockIdx.x * 256 + threadIdx.x;
    if (i < n4) {
        float4 gv = ((const float4*)g)[i];
        float4 uv = ((const float4*)u)[i];
        float4 v;
        v.x = siluf(gv.x) * uv.x; v.y = siluf(gv.y) * uv.y;
        v.z = siluf(gv.z) * uv.z; v.w = siluf(gv.w) * uv.w;
        uint32_t h0, l0, h1, l1;
        split_bf16(v.x, v.y, h0, l0);
        split_bf16(v.z, v.w, h1, l1);
        ((uint2*)oh)[i] = make_uint2(h0, h1);
        ((uint2*)ol)[i] = make_uint2(l0, l1);
    }
}

// ---------------- gated rmsnorm over D_INNER=2048, writes split-bf16 ----------------
__global__ void __launch_bounds__(256) gated_rmsnorm(const float* __restrict__ y,
                                                     const float* __restrict__ Z,
                                                     const float* __restrict__ w,
                                                     __nv_bfloat16* __restrict__ oh,
                                                     __nv_bfloat16* __restrict__ ol) {
    int tok = blockIdx.x;
    int tid = threadIdx.x;
    const float4* yp = (const float4*)(y + (size_t)tok * DINNER);
    const float4* zp = (const float4*)(Z + (size_t)tok * DINPROJ);
    float4 v[2];
    float ss = 0.f;
    #pragma unroll
    for (int q = 0; q < 2; q++) {
        float4 yv = yp[tid + q * 256];
        float4 zv = zp[tid + q * 256];
        float4 t;
        t.x = yv.x * siluf(zv.x); t.y = yv.y * siluf(zv.y);
        t.z = yv.z * siluf(zv.z); t.w = yv.w * siluf(zv.w);
        v[q] = t;
        ss += t.x * t.x + t.y * t.y + t.z * t.z + t.w * t.w;
    }
    ss = blockReduceSum(ss);
    float rs = rsqrtf(ss * (1.0f / DINNER) + EPSV);
    #pragma unroll
    for (int q = 0; q < 2; q++) {
        float4 wv = ((const float4*)w)[tid + q * 256];
        float4 o;
        o.x = v[q].x * rs * wv.x; o.y = v[q].y * rs * wv.y;
        o.z = v[q].z * rs * wv.z; o.w = v[q].w * rs * wv.w;
        uint32_t h0, l0, h1, l1;
        split_bf16(o.x, o.y, h0, l0);
        split_bf16(o.z, o.w, h1, l1);
        ((uint2*)(oh + (size_t)tok * DINNER))[tid + q * 256] = make_uint2(h0, h1);
        ((uint2*)(ol + (size_t)tok * DINNER))[tid + q * 256] = make_uint2(l0, l1);
    }
}

// ---------------- causal depthwise conv (width 4) + silu ----------------
__global__ void __launch_bounds__(256) conv_silu(const float* __restrict__ Z,
                                                 const float* __restrict__ cw,
                                                 const float* __restrict__ cb,
                                                 float* __restrict__ out) {
    int c   = blockIdx.x * 256 + threadIdx.x;
    int tok = blockIdx.y;
    if (c >= CONVDIM) return;
    int l = tok & (SEQLEN - 1);
    float w0 = cw[c * 4 + 0], w1 = cw[c * 4 + 1], w2 = cw[c * 4 + 2], w3 = cw[c * 4 + 3];
    const float* zc = Z + (size_t)tok * DINPROJ + DINNER + c;
    float acc = cb[c];
    acc += zc[0] * w3;
    if (l >= 1) acc += zc[-(ptrdiff_t)DINPROJ]     * w2;
    if (l >= 2) acc += zc[-(ptrdiff_t)DINPROJ * 2] * w1;
    if (l >= 3) acc += zc[-(ptrdiff_t)DINPROJ * 3] * w0;
    out[(size_t)tok * CONVDIM + c] = siluf(acc);
}

// ---------------- sequential SSM scan: 8-way p-split, 512 blocks ----------------
__global__ void __launch_bounds__(128) ssm_scan(const float* __restrict__ xBC,
                                                const float* __restrict__ Z,
                                                const float* __restrict__ dt_bias,
                                                const float* __restrict__ A_log,
                                                const float* __restrict__ Dp,
                                                float* __restrict__ y) {
    int bid   = blockIdx.x;          // 512 = b(2) * h(32) * oct(8)
    int b     = bid >> 8;
    int h     = (bid >> 3) & 31;
    int oct   = bid & 7;
    int pbase = oct * 8;
    int t     = threadIdx.x;

    __shared__ float s_dtx[2][2][8];
    __shared__ float s_x[2][2][8];
    __shared__ float s_red[2][8][144];

    float hs[8];
    #pragma unroll
    for (int p = 0; p < 8; p++) hs[p] = 0.f;

    float Ahv = -__expf(A_log[h]);
    float dbh = dt_bias[h];
    float Dh  = Dp[h];
    int   rp  = t >> 4;
    int   ri  = t & 15;

    const float* xrow  = xBC + (size_t)b * SEQLEN * CONVDIM;
    const float* dtrow = Z + (size_t)b * SEQLEN * DINPROJ + (DINPROJ - NHEADS) + h;
    float*       yrow  = y + (size_t)b * SEQLEN * DINNER + h * HEADDIM + pbase;

    float Bv[2], Cv[2], dAc[2];
    float B1[2], C1[2], dt1[2], x1v[2];

    #pragma unroll
    for (int q = 0; q < 2; q++) {
        const float* xr = xrow + (size_t)q * CONVDIM;
        Bv[q] = xr[DINNER + t];
        Cv[q] = xr[DINNER + DSTATE + t];
        float dts = dtrow[(size_t)q * DINPROJ] + dbh;
        float dtv = (dts > 20.f) ? dts : __logf(1.f + __expf(dts));
        dAc[q] = __expf(dtv * Ahv);
        if (t < 8) {
            float x0 = xr[h * HEADDIM + pbase + t];
            s_dtx[0][q][t] = dtv * x0; s_x[0][q][t] = x0;
        }
    }
    #pragma unroll
    for (int q = 0; q < 2; q++) {
        const float* xr = xrow + (size_t)(2 + q) * CONVDIM;
        B1[q]  = xr[DINNER + t];
        C1[q]  = xr[DINNER + DSTATE + t];
        dt1[q] = dtrow[(size_t)(2 + q) * DINPROJ];
        x1v[q] = (t < 8) ? xr[h * HEADDIM + pbase + t] : 0.f;
    }
    __syncthreads();

    int cur = 0;
    for (int i = 0; i < SEQLEN / 2; i++) {
        int nxt = cur ^ 1;
        float dAn[2] = {0.f, 0.f};
        if (i < SEQLEN / 2 - 1) {
            #pragma unroll
            for (int q = 0; q < 2; q++) {
                float dts = dt1[q] + dbh;
                float dtv = (dts > 20.f) ? dts : __logf(1.f + __expf(dts));
                dAn[q] = __expf(dtv * Ahv);
                if (t < 8) { s_dtx[nxt][q][t] = dtv * x1v[q]; s_x[nxt][q][t] = x1v[q]; }
            }
        }
        #pragma unroll
        for (int q = 0; q < 2; q++) {
            float dAq = dAc[q], Bq = Bv[q], Cq = Cv[q];
            #pragma unroll
            for (int p = 0; p < 8; p++) {
                hs[p] = fmaf(hs[p], dAq, s_dtx[cur][q][p] * Bq);
                s_red[q][p][t] = hs[p] * Cq;
            }
        }
        __syncthreads();

        #pragma unroll
        for (int q = 0; q < 2; q++) {
            float sum = 0.f;
            #pragma unroll
            for (int k = 0; k < 8; k++) sum += s_red[q][rp][k * 16 + ri];
            #pragma unroll
            for (int o = 8; o; o >>= 1) sum += __shfl_xor_sync(0xffffffffu, sum, o, 16);
            if (ri == 0)
                yrow[(size_t)(2 * i + q) * DINNER + rp] = sum + Dh * s_x[cur][q][rp];
        }

        dAc[0] = dAn[0]; dAc[1] = dAn[1];
        Bv[0] = B1[0]; Bv[1] = B1[1];
        Cv[0] = C1[0]; Cv[1] = C1[1];
        if (i < SEQLEN / 2 - 2) {
            #pragma unroll
            for (int q = 0; q < 2; q++) {
                int s = 2 * i + 4 + q;
                const float* xr = xrow + (size_t)s * CONVDIM;
                B1[q]  = xr[DINNER + t];
                C1[q]  = xr[DINNER + DSTATE + t];
                dt1[q] = dtrow[(size_t)s * DINPROJ];
                x1v[q] = (t < 8) ? xr[h * HEADDIM + pbase + t] : 0.f;
            }
        }
        __syncthreads();
        cur = nxt;
    }
}

// ---------------- launch ----------------
extern "C" void kernel_launch(void* const* d_in, const int* in_sizes, int n_in,
                              void* d_out, int out_size) {
    const float* hidden     = (const float*)d_in[0];
    const float* norm_w     = (const float*)d_in[1];
    const float* in_proj_w  = (const float*)d_in[2];
    const float* conv_w     = (const float*)d_in[3];
    const float* conv_b     = (const float*)d_in[4];
    const float* dt_bias    = (const float*)d_in[5];
    const float* A_log      = (const float*)d_in[6];
    const float* Dvec       = (const float*)d_in[7];
    const float* ssm_norm_w = (const float*)d_in[8];
    const float* out_proj_w = (const float*)d_in[9];
    const float* post_norm_w= (const float*)d_in[10];
    const float* gate_w     = (const float*)d_in[11];
    const float* up_w       = (const float*)d_in[12];
    const float* down_w     = (const float*)d_in[13];
    float* out = (float*)d_out;

    float *Z, *xBC, *y, *x2, *gg, *uu;
    cudaGetSymbolAddress((void**)&Z,   g_Z);
    cudaGetSymbolAddress((void**)&xBC, g_xBC);
    cudaGetSymbolAddress((void**)&y,   g_y);
    cudaGetSymbolAddress((void**)&x2,  g_x2);
    cudaGetSymbolAddress((void**)&gg,  g_g);
    cudaGetSymbolAddress((void**)&uu,  g_u);

    __nv_bfloat16 *x1h, *x1l, *h2h, *h2l, *y2h, *y2l, *ddh, *ddl;
    cudaGetSymbolAddress((void**)&x1h, g_x1h); cudaGetSymbolAddress((void**)&x1l, g_x1l);
    cudaGetSymbolAddress((void**)&h2h, g_h2h); cudaGetSymbolAddress((void**)&h2l, g_h2l);
    cudaGetSymbolAddress((void**)&y2h, g_y2h); cudaGetSymbolAddress((void**)&y2l, g_y2l);
    cudaGetSymbolAddress((void**)&ddh, g_ddh); cudaGetSymbolAddress((void**)&ddl, g_ddl);

    __nv_bfloat16 *wih, *wil, *woh, *wol, *wgh, *wgl, *wuh, *wul, *wdh, *wdl;
    cudaGetSymbolAddress((void**)&wih, g_wih); cudaGetSymbolAddress((void**)&wil, g_wil);
    cudaGetSymbolAddress((void**)&woh, g_woh); cudaGetSymbolAddress((void**)&wol, g_wol);
    cudaGetSymbolAddress((void**)&wgh, g_wgh); cudaGetSymbolAddress((void**)&wgl, g_wgl);
    cudaGetSymbolAddress((void**)&wuh, g_wuh); cudaGetSymbolAddress((void**)&wul, g_wul);
    cudaGetSymbolAddress((void**)&wdh, g_wdh); cudaGetSymbolAddress((void**)&wdl, g_wdl);

    cudaFuncSetAttribute(gemm_bf16, cudaFuncAttributeMaxDynamicSharedMemorySize, GEMM_SMEM);

    const int nIn = DINPROJ * DMODEL / 4, nOut = DMODEL * DINNER / 4;
    const int nGU = INTERD * DMODEL / 4,  nDn  = DMODEL * INTERD / 4;

    // 0,1: weight pre-conversion
    wsplit3<<<(nIn + nOut + nGU + 255) / 256, 256>>>(
        in_proj_w, wih, wil, nIn, out_proj_w, woh, wol, nOut, gate_w, wgh, wgl, nGU);
    wsplit3<<<(nGU + nDn + 255) / 256, 256>>>(
        up_w, wuh, wul, nGU, down_w, wdh, wdl, nDn, nullptr, nullptr, nullptr, 0);

    // 2: pre-norm
    rmsnorm1024<<<NTOK, 256>>>(hidden, norm_w, x1h, x1l);
    // 3: in_proj -> Z
    gemm_bf16<<<dim3((DINPROJ + 127) / 128, NTOK / 128, 1), 256, GEMM_SMEM>>>(
        x1h, x1l, wih, wil, nullptr, nullptr, Z, nullptr, NTOK, DINPROJ, DMODEL, 1);
    // 4: causal conv + silu
    conv_silu<<<dim3((CONVDIM + 255) / 256, NTOK), 256>>>(Z, conv_w, conv_b, xBC);
    // 5: SSM scan (+ D skip)
    ssm_scan<<<512, 128>>>(xBC, Z, dt_bias, A_log, Dvec, y);
    // 6: gated rmsnorm -> y2 split    (Z's z-gate consumed here; Z dead after)
    gated_rmsnorm<<<NTOK, 256>>>(y, Z, ssm_norm_w, y2h, y2l);
    // 7: out_proj split-K2 -> partials in Z scratch
    gemm_bf16<<<dim3(DMODEL / 128, NTOK / 128, 2), 256, GEMM_SMEM>>>(
        y2h, y2l, woh, wol, nullptr, nullptr, Z, nullptr, NTOK, DMODEL, DINNER, 2);
    // 8: x2 = hidden + p0 + p1; post-norm -> h2 split
    rmsnorm_sum3<<<NTOK, 256>>>(hidden, Z, Z + (size_t)NTOK * DMODEL, post_norm_w,
                                x2, h2h, h2l);
    // 9: gate & up fused in one launch (z selects weight/output)
    gemm_bf16<<<dim3((INTERD + 127) / 128, NTOK / 128, 2), 256, GEMM_SMEM>>>(
        h2h, h2l, wgh, wgl, wuh, wul, gg, uu, NTOK, INTERD, DMODEL, 1);
    // 10: swiglu + split -> dd
    swiglu_split<<<(NTOK * INTERD / 4 + 255) / 256, 256>>>(
        gg, uu, ddh, ddl, NTOK * INTERD / 4);
    // 11: down proj split-K2 -> partials in gg scratch
    gemm_bf16<<<dim3(DMODEL / 128, NTOK / 128, 2), 256, GEMM_SMEM>>>(
        ddh, ddl, wdh, wdl, nullptr, nullptr, gg, nullptr, NTOK, DMODEL, INTERD, 2);
    // 12: out = x2 + p0 + p1
    add3<<<(NTOK * DMODEL / 4 + 255) / 256, 256>>>(
        x2, gg, gg + (size_t)NTOK * DMODEL, out, NTOK * DMODEL / 4);
}